// round 7
// baseline (speedup 1.0000x reference)
#include <cuda_runtime.h>
#include <cuda_bf16.h>
#include <cstdint>
#include <math.h>

#define SEQ  2048
#define DM   1024
#define TDM  3072
#define NH   16
#define DH   64
#define MAXD 128

typedef unsigned long long ull;

// ---------------- scratch ---------------------------------------------------
__device__ float g_qkv[SEQ * TDM];   // [s][3*d_model]
__device__ float g_attn[SEQ * DM];   // [s][h*64+d]

// ---------------- helpers ---------------------------------------------------
__device__ __forceinline__ uint32_t smem_u32(const void* p) {
    uint32_t a;
    asm("{ .reg .u64 t; cvta.to.shared.u64 t, %1; cvt.u32.u64 %0, t; }" : "=r"(a) : "l"(p));
    return a;
}
__device__ __forceinline__ void ldsm_x4(uint32_t& r0, uint32_t& r1, uint32_t& r2,
                                        uint32_t& r3, uint32_t addr) {
    asm volatile("ldmatrix.sync.aligned.m8n8.x4.shared.b16 {%0,%1,%2,%3}, [%4];"
                 : "=r"(r0), "=r"(r1), "=r"(r2), "=r"(r3) : "r"(addr));
}
__device__ __forceinline__ void ldsm_x4t(uint32_t& r0, uint32_t& r1, uint32_t& r2,
                                         uint32_t& r3, uint32_t addr) {
    asm volatile("ldmatrix.sync.aligned.m8n8.x4.trans.shared.b16 {%0,%1,%2,%3}, [%4];"
                 : "=r"(r0), "=r"(r1), "=r"(r2), "=r"(r3) : "r"(addr));
}
__device__ __forceinline__ void mma16816(float* d, const uint32_t* a, const uint32_t* b) {
    asm volatile("mma.sync.aligned.m16n8k16.row.col.f32.bf16.bf16.f32 "
                 "{%0,%1,%2,%3}, {%4,%5,%6,%7}, {%8,%9}, {%0,%1,%2,%3};"
                 : "+f"(d[0]), "+f"(d[1]), "+f"(d[2]), "+f"(d[3])
                 : "r"(a[0]), "r"(a[1]), "r"(a[2]), "r"(a[3]), "r"(b[0]), "r"(b[1]));
}
__device__ __forceinline__ uint32_t bf16x2_of(float lo, float hi) {
    uint32_t r;
    asm("cvt.rn.bf16x2.f32 %0, %1, %2;" : "=r"(r) : "f"(hi), "f"(lo));
    return r;
}
__device__ __forceinline__ void pack_hilo(float x, float y, uint32_t& ph, uint32_t& pl) {
    __nv_bfloat16 hx = __float2bfloat16_rn(x);
    __nv_bfloat16 hy = __float2bfloat16_rn(y);
    float fx = __bfloat162float(hx), fy = __bfloat162float(hy);
    ph = ((uint32_t)__bfloat16_as_ushort(hy) << 16) | (uint32_t)__bfloat16_as_ushort(hx);
    pl = bf16x2_of(x - fx, y - fy);
}
__device__ __forceinline__ void sts_split4(char* hi_base, char* lo_base,
                                           int row, int col, int stride, float4 v) {
    uint32_t h0, l0, h1, l1;
    pack_hilo(v.x, v.y, h0, l0);
    pack_hilo(v.z, v.w, h1, l1);
    char* ph = hi_base + (row * stride + col) * 2;
    char* pl = lo_base + (row * stride + col) * 2;
    *(uint32_t*)(ph)     = h0;
    *(uint32_t*)(ph + 4) = h1;
    *(uint32_t*)(pl)     = l0;
    *(uint32_t*)(pl + 4) = l1;
}

// ---------------------------------------------------------------------------
// Split-bf16 mma.sync GEMM: C[M,N] = A[M,K] @ B[K,N].
// MMA issue interleaved across 4 accumulators (distance-4 RAW chains).
// ---------------------------------------------------------------------------
#define SA 40
#define SB 136
#define A_TILE_B (128 * SA * 2)
#define B_TILE_B (32 * SB * 2)
#define STAGE_B  (2 * A_TILE_B + 2 * B_TILE_B)
#define GSMEM    (2 * STAGE_B)

__global__ __launch_bounds__(256)
void gemm_mma(const float* __restrict__ A, const float* __restrict__ B,
              float* __restrict__ C, int M, int N, int K) {
    extern __shared__ char smem[];
    const int tid  = threadIdx.x;
    const int lane = tid & 31;
    const int wid  = tid >> 5;
    const int wm   = wid & 3;
    const int wn   = wid >> 2;
    const int bm = blockIdx.y * 128;
    const int bn = blockIdx.x * 128;

    const int ar = tid >> 1;
    const int ak = (tid & 1) * 16;
    const int br = tid >> 3;
    const int bc = (tid & 7) * 16;

    const float* Ap = A + (ull)(bm + ar) * K + ak;
    const float* Bp = B + (ull)br * N + bn + bc;

    float4 areg[4], breg[4];
#pragma unroll
    for (int i = 0; i < 4; i++) {
        areg[i] = *(const float4*)(Ap + i * 4);
        breg[i] = *(const float4*)(Bp + i * 4);
    }

    float acc[2][8][4];
#pragma unroll
    for (int mt = 0; mt < 2; mt++)
#pragma unroll
        for (int nt = 0; nt < 8; nt++)
#pragma unroll
            for (int e = 0; e < 4; e++) acc[mt][nt][e] = 0.f;

    const uint32_t smem_b = smem_u32(smem);
    const int NT = K / 32;

    for (int t = 0; t < NT; t++) {
        const uint32_t stg = smem_b + (t & 1) * STAGE_B;
        {
            char* Ahi = smem + (t & 1) * STAGE_B;
            char* Alo = Ahi + A_TILE_B;
            char* Bhi = Ahi + 2 * A_TILE_B;
            char* Blo = Bhi + B_TILE_B;
#pragma unroll
            for (int i = 0; i < 4; i++) {
                sts_split4(Ahi, Alo, ar, ak + i * 4, SA, areg[i]);
                sts_split4(Bhi, Blo, br, bc + i * 4, SB, breg[i]);
            }
        }
        __syncthreads();

        if (t + 1 < NT) {
#pragma unroll
            for (int i = 0; i < 4; i++) {
                areg[i] = *(const float4*)(Ap + (t + 1) * 32 + i * 4);
                breg[i] = *(const float4*)(Bp + (ull)(t + 1) * 32 * N + i * 4);
            }
        }

        const uint32_t uAhi = stg;
        const uint32_t uAlo = stg + A_TILE_B;
        const uint32_t uBhi = stg + 2 * A_TILE_B;
        const uint32_t uBlo = uBhi + B_TILE_B;
#pragma unroll
        for (int ks = 0; ks < 2; ks++) {
            const int k0 = ks * 16;
            uint32_t afh[2][4], afl[2][4];
#pragma unroll
            for (int mt = 0; mt < 2; mt++) {
                const int row = wm * 32 + mt * 16 + (lane & 15);
                const int col = k0 + ((lane >> 4) << 3);
                const uint32_t off = (uint32_t)(row * SA + col) * 2;
                ldsm_x4(afh[mt][0], afh[mt][1], afh[mt][2], afh[mt][3], uAhi + off);
                ldsm_x4(afl[mt][0], afl[mt][1], afl[mt][2], afl[mt][3], uAlo + off);
            }
#pragma unroll
            for (int g = 0; g < 4; g++) {
                uint32_t bh[4], bl[4];
                const int row = k0 + (lane & 15);
                const int col = wn * 64 + g * 16 + ((lane >> 4) << 3);
                const uint32_t off = (uint32_t)(row * SB + col) * 2;
                ldsm_x4t(bh[0], bh[1], bh[2], bh[3], uBhi + off);
                ldsm_x4t(bl[0], bl[1], bl[2], bl[3], uBlo + off);
                // hh round (distance-4 chains)
                mma16816(acc[0][2 * g],     afh[0], &bh[0]);
                mma16816(acc[0][2 * g + 1], afh[0], &bh[2]);
                mma16816(acc[1][2 * g],     afh[1], &bh[0]);
                mma16816(acc[1][2 * g + 1], afh[1], &bh[2]);
                // hl round
                mma16816(acc[0][2 * g],     afh[0], &bl[0]);
                mma16816(acc[0][2 * g + 1], afh[0], &bl[2]);
                mma16816(acc[1][2 * g],     afh[1], &bl[0]);
                mma16816(acc[1][2 * g + 1], afh[1], &bl[2]);
                // lh round
                mma16816(acc[0][2 * g],     afl[0], &bh[0]);
                mma16816(acc[0][2 * g + 1], afl[0], &bh[2]);
                mma16816(acc[1][2 * g],     afl[1], &bh[0]);
                mma16816(acc[1][2 * g + 1], afl[1], &bh[2]);
            }
        }
        __syncthreads();
    }

    const int group = lane >> 2;
    const int tq = lane & 3;
#pragma unroll
    for (int mt = 0; mt < 2; mt++) {
#pragma unroll
        for (int nt = 0; nt < 8; nt++) {
            const int row = bm + wm * 32 + mt * 16 + group;
            const int col = bn + wn * 64 + nt * 8 + tq * 2;
            *(float2*)&C[(ull)row * N + col] =
                make_float2(acc[mt][nt][0], acc[mt][nt][1]);
            *(float2*)&C[(ull)(row + 8) * N + col] =
                make_float2(acc[mt][nt][2], acc[mt][nt][3]);
        }
    }
}

// ---------------------------------------------------------------------------
// HMMA flash attention, split-bf16 3-term; MMA issue interleaved (distance 4).
// ---------------------------------------------------------------------------
#define QSTR 72
#define OFF_QH 0
#define OFF_QL 9216
#define OFF_KH 18432
#define OFF_KL 27648
#define OFF_VH 36864
#define OFF_VL 46080
#define OFF_BIAS 55296
#define OFF_RM 55808
#define OFF_RS 56320
#define ATT_SMEM 56832
#define OFF_OEP OFF_KH

__global__ __launch_bounds__(256)
void attn_mma(const float* __restrict__ qkv, const float* __restrict__ rel_bias,
              float* __restrict__ out) {
    extern __shared__ char sm[];
    const uint32_t sb = smem_u32(sm);
    const int tid  = threadIdx.x;
    const int lane = tid & 31;
    const int wid  = tid >> 5;
    const int wm   = wid & 3;
    const int wn   = wid >> 2;
    const int h  = blockIdx.y;
    const int q0 = blockIdx.x * 64;

    float* redM   = (float*)(sm + OFF_RM);
    float* redS   = (float*)(sm + OFF_RS);
    float* bias_s = (float*)(sm + OFF_BIAS);
    if (tid < MAXD) bias_s[tid] = rel_bias[tid * NH + h];

    const int grow = tid >> 2;
    const int gcol = (tid & 3) * 16;

    {
        const float* Qp = qkv + (ull)(q0 + grow) * TDM + h * DH + gcol;
#pragma unroll
        for (int i = 0; i < 4; i++)
            sts_split4(sm + OFF_QH, sm + OFF_QL, grow, gcol + i * 4, QSTR,
                       *(const float4*)(Qp + i * 4));
    }

    float4 kreg[4], vreg[4];
    {
        const float* Kp = qkv + (ull)grow * TDM + DM + h * DH + gcol;
        const float* Vp = qkv + (ull)grow * TDM + 2 * DM + h * DH + gcol;
#pragma unroll
        for (int i = 0; i < 4; i++) {
            kreg[i] = *(const float4*)(Kp + i * 4);
            vreg[i] = *(const float4*)(Vp + i * 4);
        }
    }

    float m_a = -1e30f, m_b = -1e30f, l_a = 0.f, l_b = 0.f;
    float accO[8][4];
#pragma unroll
    for (int d = 0; d < 8; d++)
#pragma unroll
        for (int e = 0; e < 4; e++) accO[d][e] = 0.f;

    const int qa_row   = wm * 16 + (lane & 15);
    const int qa_coff  = (lane >> 4) << 3;
    const int kb_key   = wn * 32 + ((lane >> 4) << 3) + (lane & 7);
    const int kb_coff  = ((lane >> 3) & 1) << 3;
    const int vb_key   = wn * 32 + (lane & 15);
    const int vb_coff  = (lane >> 4) << 3;
    const int rA = wm * 16 + (lane >> 2);
    const int rB = rA + 8;
    const int qA = q0 + rA, qB = q0 + rB;

    for (int kt = 0; kt < SEQ / 64; kt++) {
        __syncthreads();
#pragma unroll
        for (int i = 0; i < 4; i++) {
            sts_split4(sm + OFF_KH, sm + OFF_KL, grow, gcol + i * 4, QSTR, kreg[i]);
            sts_split4(sm + OFF_VH, sm + OFF_VL, grow, gcol + i * 4, QSTR, vreg[i]);
        }
        __syncthreads();

        if (kt + 1 < SEQ / 64) {
            const ull r = (ull)((kt + 1) * 64 + grow) * TDM + h * DH + gcol;
#pragma unroll
            for (int i = 0; i < 4; i++) {
                kreg[i] = *(const float4*)(qkv + r + DM + i * 4);
                vreg[i] = *(const float4*)(qkv + r + 2 * DM + i * 4);
            }
        }

        // ---- S = Q K^T (12 MMAs per ks, distance-4 chains) ----
        float sS[4][4];
#pragma unroll
        for (int f = 0; f < 4; f++)
#pragma unroll
            for (int e = 0; e < 4; e++) sS[f][e] = 0.f;

#pragma unroll
        for (int ks = 0; ks < 4; ks++) {
            const uint32_t qoff = (uint32_t)(qa_row * QSTR + ks * 16 + qa_coff) * 2;
            uint32_t qh[4], ql[4];
            ldsm_x4(qh[0], qh[1], qh[2], qh[3], sb + OFF_QH + qoff);
            ldsm_x4(ql[0], ql[1], ql[2], ql[3], sb + OFF_QL + qoff);
            const uint32_t koff0 = (uint32_t)(kb_key * QSTR + ks * 16 + kb_coff) * 2;
            const uint32_t koff1 = (uint32_t)((kb_key + 16) * QSTR + ks * 16 + kb_coff) * 2;
            uint32_t kh0[4], kl0[4], kh1[4], kl1[4];
            ldsm_x4(kh0[0], kh0[1], kh0[2], kh0[3], sb + OFF_KH + koff0);
            ldsm_x4(kl0[0], kl0[1], kl0[2], kl0[3], sb + OFF_KL + koff0);
            ldsm_x4(kh1[0], kh1[1], kh1[2], kh1[3], sb + OFF_KH + koff1);
            ldsm_x4(kl1[0], kl1[1], kl1[2], kl1[3], sb + OFF_KL + koff1);
            // hh
            mma16816(sS[0], qh, &kh0[0]);
            mma16816(sS[1], qh, &kh0[2]);
            mma16816(sS[2], qh, &kh1[0]);
            mma16816(sS[3], qh, &kh1[2]);
            // hl
            mma16816(sS[0], qh, &kl0[0]);
            mma16816(sS[1], qh, &kl0[2]);
            mma16816(sS[2], qh, &kl1[0]);
            mma16816(sS[3], qh, &kl1[2]);
            // lh
            mma16816(sS[0], ql, &kh0[0]);
            mma16816(sS[1], ql, &kh0[2]);
            mma16816(sS[2], ql, &kh1[0]);
            mma16816(sS[3], ql, &kh1[2]);
        }

        // ---- scale + relative bias ----
        const int kbase = kt * 64 + wn * 32 + (lane & 3) * 2;
#pragma unroll
        for (int f = 0; f < 4; f++) {
#pragma unroll
            for (int e = 0; e < 2; e++) {
                const int kg = kbase + f * 8 + e;
                int dA = kg - qA; dA = dA < 0 ? -dA : dA; if (dA > MAXD - 1) dA = MAXD - 1;
                int dB = kg - qB; dB = dB < 0 ? -dB : dB; if (dB > MAXD - 1) dB = MAXD - 1;
                sS[f][e]     = fmaf(sS[f][e],     0.125f, bias_s[dA]);
                sS[f][2 + e] = fmaf(sS[f][2 + e], 0.125f, bias_s[dB]);
            }
        }

        // ---- online softmax ----
        float mxA = fmaxf(fmaxf(sS[0][0], sS[0][1]), fmaxf(sS[1][0], sS[1][1]));
        mxA = fmaxf(mxA, fmaxf(fmaxf(sS[2][0], sS[2][1]), fmaxf(sS[3][0], sS[3][1])));
        float mxB = fmaxf(fmaxf(sS[0][2], sS[0][3]), fmaxf(sS[1][2], sS[1][3]));
        mxB = fmaxf(mxB, fmaxf(fmaxf(sS[2][2], sS[2][3]), fmaxf(sS[3][2], sS[3][3])));
        mxA = fmaxf(mxA, __shfl_xor_sync(0xffffffffu, mxA, 1));
        mxA = fmaxf(mxA, __shfl_xor_sync(0xffffffffu, mxA, 2));
        mxB = fmaxf(mxB, __shfl_xor_sync(0xffffffffu, mxB, 1));
        mxB = fmaxf(mxB, __shfl_xor_sync(0xffffffffu, mxB, 2));
        if ((lane & 3) == 0) { redM[wn * 64 + rA] = mxA; redM[wn * 64 + rB] = mxB; }
        __syncthreads();
        mxA = fmaxf(redM[rA], redM[64 + rA]);
        mxB = fmaxf(redM[rB], redM[64 + rB]);

        const float mnA = fmaxf(m_a, mxA), mnB = fmaxf(m_b, mxB);
        const float facA = __expf(m_a - mnA), facB = __expf(m_b - mnB);
        m_a = mnA; m_b = mnB;

        float sumA = 0.f, sumB = 0.f;
#pragma unroll
        for (int f = 0; f < 4; f++) {
#pragma unroll
            for (int e = 0; e < 2; e++) {
                sS[f][e]     = __expf(sS[f][e]     - m_a); sumA += sS[f][e];
                sS[f][2 + e] = __expf(sS[f][2 + e] - m_b); sumB += sS[f][2 + e];
            }
        }
        sumA += __shfl_xor_sync(0xffffffffu, sumA, 1);
        sumA += __shfl_xor_sync(0xffffffffu, sumA, 2);
        sumB += __shfl_xor_sync(0xffffffffu, sumB, 1);
        sumB += __shfl_xor_sync(0xffffffffu, sumB, 2);
        if ((lane & 3) == 0) { redS[wn * 64 + rA] = sumA; redS[wn * 64 + rB] = sumB; }
        __syncthreads();
        sumA = redS[rA] + redS[64 + rA];
        sumB = redS[rB] + redS[64 + rB];
        l_a = l_a * facA + sumA;
        l_b = l_b * facB + sumB;

#pragma unroll
        for (int d = 0; d < 8; d++) {
            accO[d][0] *= facA; accO[d][1] *= facA;
            accO[d][2] *= facB; accO[d][3] *= facB;
        }

        // ---- O += P V (12 MMAs per (ks2,dg-pair), distance-4 chains) ----
#pragma unroll
        for (int ks2 = 0; ks2 < 2; ks2++) {
            uint32_t aH[4], aL[4];
            pack_hilo(sS[2 * ks2][0],     sS[2 * ks2][1],     aH[0], aL[0]);
            pack_hilo(sS[2 * ks2][2],     sS[2 * ks2][3],     aH[1], aL[1]);
            pack_hilo(sS[2 * ks2 + 1][0], sS[2 * ks2 + 1][1], aH[2], aL[2]);
            pack_hilo(sS[2 * ks2 + 1][2], sS[2 * ks2 + 1][3], aH[3], aL[3]);
            const int vrow = vb_key + ks2 * 16;
#pragma unroll
            for (int dp = 0; dp < 2; dp++) {
                const uint32_t voff0 =
                    (uint32_t)(vrow * QSTR + (2 * dp) * 16 + vb_coff) * 2;
                const uint32_t voff1 =
                    (uint32_t)(vrow * QSTR + (2 * dp + 1) * 16 + vb_coff) * 2;
                uint32_t vh0[4], vl0[4], vh1[4], vl1[4];
                ldsm_x4t(vh0[0], vh0[1], vh0[2], vh0[3], sb + OFF_VH + voff0);
                ldsm_x4t(vl0[0], vl0[1], vl0[2], vl0[3], sb + OFF_VL + voff0);
                ldsm_x4t(vh1[0], vh1[1], vh1[2], vh1[3], sb + OFF_VH + voff1);
                ldsm_x4t(vl1[0], vl1[1], vl1[2], vl1[3], sb + OFF_VL + voff1);
                // hh
                mma16816(accO[4 * dp],     aH, &vh0[0]);
                mma16816(accO[4 * dp + 1], aH, &vh0[2]);
                mma16816(accO[4 * dp + 2], aH, &vh1[0]);
                mma16816(accO[4 * dp + 3], aH, &vh1[2]);
                // hl
                mma16816(accO[4 * dp],     aH, &vl0[0]);
                mma16816(accO[4 * dp + 1], aH, &vl0[2]);
                mma16816(accO[4 * dp + 2], aH, &vl1[0]);
                mma16816(accO[4 * dp + 3], aH, &vl1[2]);
                // lh
                mma16816(accO[4 * dp],     aL, &vh0[0]);
                mma16816(accO[4 * dp + 1], aL, &vh0[2]);
                mma16816(accO[4 * dp + 2], aL, &vh1[0]);
                mma16816(accO[4 * dp + 3], aL, &vh1[2]);
            }
        }
    }

    // ---- epilogue ----
    __syncthreads();
    float* Oep = (float*)(sm + OFF_OEP);
    const int ecol = (lane & 3) * 2;
    if (wn == 1) {
#pragma unroll
        for (int d = 0; d < 8; d++) {
            *(float2*)&Oep[rA * 68 + d * 8 + ecol] = make_float2(accO[d][0], accO[d][1]);
            *(float2*)&Oep[rB * 68 + d * 8 + ecol] = make_float2(accO[d][2], accO[d][3]);
        }
    }
    __syncthreads();
    if (wn == 0) {
        const float invA = 1.f / l_a, invB = 1.f / l_b;
#pragma unroll
        for (int d = 0; d < 8; d++) {
            float2 pA = *(float2*)&Oep[rA * 68 + d * 8 + ecol];
            float2 pB = *(float2*)&Oep[rB * 68 + d * 8 + ecol];
            *(float2*)&out[(ull)qA * DM + h * DH + d * 8 + ecol] =
                make_float2((accO[d][0] + pA.x) * invA, (accO[d][1] + pA.y) * invA);
            *(float2*)&out[(ull)qB * DM + h * DH + d * 8 + ecol] =
                make_float2((accO[d][2] + pB.x) * invB, (accO[d][3] + pB.y) * invB);
        }
    }
}

// ---------------------------------------------------------------------------
extern "C" void kernel_launch(void* const* d_in, const int* in_sizes, int n_in,
                              void* d_out, int out_size) {
    const float* x        = (const float*)d_in[0];
    const float* w_qkv    = (const float*)d_in[1];
    const float* w_out    = (const float*)d_in[2];
    const float* rel_bias = (const float*)d_in[3];
    float* out = (float*)d_out;

    float *qkv = nullptr, *attn = nullptr;
    cudaGetSymbolAddress((void**)&qkv,  g_qkv);
    cudaGetSymbolAddress((void**)&attn, g_attn);

    cudaFuncSetAttribute(gemm_mma, cudaFuncAttributeMaxDynamicSharedMemorySize, GSMEM);
    cudaFuncSetAttribute(attn_mma, cudaFuncAttributeMaxDynamicSharedMemorySize, ATT_SMEM);

    // 1) qkv = x @ w_qkv
    gemm_mma<<<dim3(TDM / 128, SEQ / 128), 256, GSMEM>>>(x, w_qkv, qkv, SEQ, TDM, DM);

    // 2) attention (HMMA flash)
    attn_mma<<<dim3(SEQ / 64, NH), 256, ATT_SMEM>>>(qkv, rel_bias, attn);

    // 3) out = attn @ w_out
    gemm_mma<<<dim3(DM / 128, SEQ / 128), 256, GSMEM>>>(attn, w_out, out, SEQ, DM, DM);
}

// round 8
// speedup vs baseline: 1.2534x; 1.2534x over previous
#include <cuda_runtime.h>
#include <cuda_bf16.h>
#include <cstdint>
#include <math.h>

#define SEQ  2048
#define DM   1024
#define TDM  3072
#define NH   16
#define DH   64
#define MAXD 128

typedef unsigned long long ull;
typedef unsigned short u16;

// ---------------- persistent scratch (bf16 hi/lo split form) ----------------
__device__ u16 g_xh[SEQ * DM],  g_xl[SEQ * DM];
__device__ u16 g_wqh[DM * TDM], g_wql[DM * TDM];
__device__ u16 g_woh[DM * DM],  g_wol[DM * DM];
__device__ u16 g_qkvh[SEQ * TDM], g_qkvl[SEQ * TDM];
__device__ u16 g_ath[SEQ * DM],   g_atl[SEQ * DM];

// ---------------- helpers ---------------------------------------------------
__device__ __forceinline__ uint32_t smem_u32(const void* p) {
    uint32_t a;
    asm("{ .reg .u64 t; cvta.to.shared.u64 t, %1; cvt.u32.u64 %0, t; }" : "=r"(a) : "l"(p));
    return a;
}
__device__ __forceinline__ void cpa16(uint32_t dst, const void* src) {
    asm volatile("cp.async.cg.shared.global [%0], [%1], 16;" :: "r"(dst), "l"(src));
}
#define CPA_COMMIT() asm volatile("cp.async.commit_group;" ::: "memory")
#define CPA_WAIT0()  asm volatile("cp.async.wait_group 0;" ::: "memory")

__device__ __forceinline__ void ldsm_x4(uint32_t& r0, uint32_t& r1, uint32_t& r2,
                                        uint32_t& r3, uint32_t addr) {
    asm volatile("ldmatrix.sync.aligned.m8n8.x4.shared.b16 {%0,%1,%2,%3}, [%4];"
                 : "=r"(r0), "=r"(r1), "=r"(r2), "=r"(r3) : "r"(addr));
}
__device__ __forceinline__ void ldsm_x4t(uint32_t& r0, uint32_t& r1, uint32_t& r2,
                                         uint32_t& r3, uint32_t addr) {
    asm volatile("ldmatrix.sync.aligned.m8n8.x4.trans.shared.b16 {%0,%1,%2,%3}, [%4];"
                 : "=r"(r0), "=r"(r1), "=r"(r2), "=r"(r3) : "r"(addr));
}
__device__ __forceinline__ void mma16816(float* d, const uint32_t* a, const uint32_t* b) {
    asm volatile("mma.sync.aligned.m16n8k16.row.col.f32.bf16.bf16.f32 "
                 "{%0,%1,%2,%3}, {%4,%5,%6,%7}, {%8,%9}, {%0,%1,%2,%3};"
                 : "+f"(d[0]), "+f"(d[1]), "+f"(d[2]), "+f"(d[3])
                 : "r"(a[0]), "r"(a[1]), "r"(a[2]), "r"(a[3]), "r"(b[0]), "r"(b[1]));
}
__device__ __forceinline__ uint32_t bf16x2_of(float lo, float hi) {
    uint32_t r;
    asm("cvt.rn.bf16x2.f32 %0, %1, %2;" : "=r"(r) : "f"(hi), "f"(lo));
    return r;
}
__device__ __forceinline__ void pack_hilo(float x, float y, uint32_t& ph, uint32_t& pl) {
    __nv_bfloat16 hx = __float2bfloat16_rn(x);
    __nv_bfloat16 hy = __float2bfloat16_rn(y);
    float fx = __bfloat162float(hx), fy = __bfloat162float(hy);
    ph = ((uint32_t)__bfloat16_as_ushort(hy) << 16) | (uint32_t)__bfloat16_as_ushort(hx);
    pl = bf16x2_of(x - fx, y - fy);
}

// ---------------------------------------------------------------------------
// One-time fp32 -> (hi,lo) bf16 split.
// ---------------------------------------------------------------------------
__global__ __launch_bounds__(256)
void conv_split(const float* __restrict__ src, u16* __restrict__ hi,
                u16* __restrict__ lo, int n) {
    int i = (blockIdx.x * 256 + threadIdx.x) * 4;
    if (i < n) {
        float4 v = *(const float4*)(src + i);
        uint32_t h0, l0, h1, l1;
        pack_hilo(v.x, v.y, h0, l0);
        pack_hilo(v.z, v.w, h1, l1);
        *(uint32_t*)(hi + i)     = h0;
        *(uint32_t*)(hi + i + 2) = h1;
        *(uint32_t*)(lo + i)     = l0;
        *(uint32_t*)(lo + i + 2) = l1;
    }
}

// ---------------------------------------------------------------------------
// Pure-bf16 split GEMM: C = A @ B, A/B pre-split (hi,lo). cp.async pipeline.
// CTA 128x128, BK=32, 8 warps (4x2), 3-term MMA. WRITE_BF16: C -> (Ch,Cl).
// ---------------------------------------------------------------------------
#define SA 40
#define SB 136
#define A_T_B 10240                 // 128*40*2
#define B_T_B 8704                  // 32*136*2
#define STAGE_B (2 * A_T_B + 2 * B_T_B)   // 37888
#define GSMEM   (2 * STAGE_B)             // 75776

template <bool WRITE_BF16>
__global__ __launch_bounds__(256, 2)
void gemm_bf16(const u16* __restrict__ Ah, const u16* __restrict__ Al,
               const u16* __restrict__ Bh, const u16* __restrict__ Bl,
               float* __restrict__ Cf, u16* __restrict__ Ch, u16* __restrict__ Cl,
               int M, int N, int K) {
    extern __shared__ char smem[];
    const uint32_t smem_b = smem_u32(smem);
    const int tid  = threadIdx.x;
    const int lane = tid & 31;
    const int wid  = tid >> 5;
    const int wm   = wid & 3;
    const int wn   = wid >> 2;
    const int bm = blockIdx.y * 128;
    const int bn = blockIdx.x * 128;

    auto load_stage = [&](int t) {
        const uint32_t stg = smem_b + (t & 1) * STAGE_B;
#pragma unroll
        for (int i = 0; i < 2; i++) {
            const int c = tid + i * 256;
            const int row = c >> 2, cc = c & 3;
            const ull sa = (ull)(bm + row) * K + t * 32 + cc * 8;
            cpa16(stg + row * 80 + cc * 16,         Ah + sa);
            cpa16(stg + A_T_B + row * 80 + cc * 16, Al + sa);
            const int rb = c >> 4, cb = c & 15;
            const ull sbp = (ull)(t * 32 + rb) * N + bn + cb * 8;
            cpa16(stg + 2 * A_T_B + rb * 272 + cb * 16,         Bh + sbp);
            cpa16(stg + 2 * A_T_B + B_T_B + rb * 272 + cb * 16, Bl + sbp);
        }
    };

    float acc[2][8][4];
#pragma unroll
    for (int mt = 0; mt < 2; mt++)
#pragma unroll
        for (int nt = 0; nt < 8; nt++)
#pragma unroll
            for (int e = 0; e < 4; e++) acc[mt][nt][e] = 0.f;

    const int NT = K / 32;
    load_stage(0);
    CPA_COMMIT();

    for (int t = 0; t < NT; t++) {
        CPA_WAIT0();
        __syncthreads();
        if (t + 1 < NT) { load_stage(t + 1); CPA_COMMIT(); }

        const uint32_t stg  = smem_b + (t & 1) * STAGE_B;
        const uint32_t uAhi = stg;
        const uint32_t uAlo = stg + A_T_B;
        const uint32_t uBhi = stg + 2 * A_T_B;
        const uint32_t uBlo = uBhi + B_T_B;
#pragma unroll
        for (int ks = 0; ks < 2; ks++) {
            const int k0 = ks * 16;
            uint32_t afh[2][4], afl[2][4];
#pragma unroll
            for (int mt = 0; mt < 2; mt++) {
                const int row = wm * 32 + mt * 16 + (lane & 15);
                const int col = k0 + ((lane >> 4) << 3);
                const uint32_t off = (uint32_t)(row * SA + col) * 2;
                ldsm_x4(afh[mt][0], afh[mt][1], afh[mt][2], afh[mt][3], uAhi + off);
                ldsm_x4(afl[mt][0], afl[mt][1], afl[mt][2], afl[mt][3], uAlo + off);
            }
#pragma unroll
            for (int g = 0; g < 4; g++) {
                uint32_t bh[4], bl[4];
                const int row = k0 + (lane & 15);
                const int col = wn * 64 + g * 16 + ((lane >> 4) << 3);
                const uint32_t off = (uint32_t)(row * SB + col) * 2;
                ldsm_x4t(bh[0], bh[1], bh[2], bh[3], uBhi + off);
                ldsm_x4t(bl[0], bl[1], bl[2], bl[3], uBlo + off);
                mma16816(acc[0][2 * g],     afh[0], &bh[0]);
                mma16816(acc[0][2 * g + 1], afh[0], &bh[2]);
                mma16816(acc[1][2 * g],     afh[1], &bh[0]);
                mma16816(acc[1][2 * g + 1], afh[1], &bh[2]);
                mma16816(acc[0][2 * g],     afh[0], &bl[0]);
                mma16816(acc[0][2 * g + 1], afh[0], &bl[2]);
                mma16816(acc[1][2 * g],     afh[1], &bl[0]);
                mma16816(acc[1][2 * g + 1], afh[1], &bl[2]);
                mma16816(acc[0][2 * g],     afl[0], &bh[0]);
                mma16816(acc[0][2 * g + 1], afl[0], &bh[2]);
                mma16816(acc[1][2 * g],     afl[1], &bh[0]);
                mma16816(acc[1][2 * g + 1], afl[1], &bh[2]);
            }
        }
    }

    // ---- epilogue ----
    const int group = lane >> 2;
    const int tq = lane & 3;
#pragma unroll
    for (int mt = 0; mt < 2; mt++) {
#pragma unroll
        for (int nt = 0; nt < 8; nt++) {
            const int row = bm + wm * 32 + mt * 16 + group;
            const int col = bn + wn * 64 + nt * 8 + tq * 2;
            if (WRITE_BF16) {
                uint32_t ph, pl;
                pack_hilo(acc[mt][nt][0], acc[mt][nt][1], ph, pl);
                *(uint32_t*)(Ch + (ull)row * N + col) = ph;
                *(uint32_t*)(Cl + (ull)row * N + col) = pl;
                pack_hilo(acc[mt][nt][2], acc[mt][nt][3], ph, pl);
                *(uint32_t*)(Ch + (ull)(row + 8) * N + col) = ph;
                *(uint32_t*)(Cl + (ull)(row + 8) * N + col) = pl;
            } else {
                *(float2*)&Cf[(ull)row * N + col] =
                    make_float2(acc[mt][nt][0], acc[mt][nt][1]);
                *(float2*)&Cf[(ull)(row + 8) * N + col] =
                    make_float2(acc[mt][nt][2], acc[mt][nt][3]);
            }
        }
    }
}

// ---------------------------------------------------------------------------
// HMMA flash attention on pre-split bf16 qkv; cp.async K/V pipeline.
// Output written as (hi,lo) bf16 for GEMM2.
// ---------------------------------------------------------------------------
#define QSTR 72
#define OFF_QH 0
#define OFF_QL 9216
#define KV_BASE 18432
#define KV_STAGE 36864            // KH(9216)+KL+VH+VL per stage
#define OFF_BIAS 92160
#define OFF_RM 92672
#define OFF_RS 93184
#define ATT_SMEM 93696
#define OFF_OEP KV_BASE           // epilogue f32 [64][68] aliases stage0 K

__global__ __launch_bounds__(256, 2)
void attn_mma(const u16* __restrict__ qkvh, const u16* __restrict__ qkvl,
              const float* __restrict__ rel_bias,
              u16* __restrict__ ath, u16* __restrict__ atl) {
    extern __shared__ char sm[];
    const uint32_t sb = smem_u32(sm);
    const int tid  = threadIdx.x;
    const int lane = tid & 31;
    const int wid  = tid >> 5;
    const int wm   = wid & 3;
    const int wn   = wid >> 2;
    const int h  = blockIdx.y;
    const int q0 = blockIdx.x * 64;

    float* redM   = (float*)(sm + OFF_RM);
    float* redS   = (float*)(sm + OFF_RS);
    float* bias_s = (float*)(sm + OFF_BIAS);
    if (tid < MAXD) bias_s[tid] = rel_bias[tid * NH + h];

    auto load_kv = [&](int kt) {
        const uint32_t sK = sb + KV_BASE + (kt & 1) * KV_STAGE;
        const ull base = (ull)(kt * 64) * TDM + h * DH;
#pragma unroll
        for (int i = 0; i < 2; i++) {
            const int c = tid + i * 256;
            const int row = c >> 3, cc = c & 7;
            const ull so = base + (ull)row * TDM + cc * 8;
            const uint32_t d = row * 144 + cc * 16;
            cpa16(sK + d,          qkvh + so + DM);
            cpa16(sK + 9216 + d,   qkvl + so + DM);
            cpa16(sK + 18432 + d,  qkvh + so + 2 * DM);
            cpa16(sK + 27648 + d,  qkvl + so + 2 * DM);
        }
    };

    // prologue: Q + KV tile 0 in one group
#pragma unroll
    for (int i = 0; i < 2; i++) {
        const int c = tid + i * 256;
        const int row = c >> 3, cc = c & 7;
        const ull so = (ull)(q0 + row) * TDM + h * DH + cc * 8;
        const uint32_t d = row * 144 + cc * 16;
        cpa16(sb + OFF_QH + d, qkvh + so);
        cpa16(sb + OFF_QL + d, qkvl + so);
    }
    load_kv(0);
    CPA_COMMIT();

    float m_a = -1e30f, m_b = -1e30f, l_a = 0.f, l_b = 0.f;
    float accO[8][4];
#pragma unroll
    for (int d = 0; d < 8; d++)
#pragma unroll
        for (int e = 0; e < 4; e++) accO[d][e] = 0.f;

    const int qa_row   = wm * 16 + (lane & 15);
    const int qa_coff  = (lane >> 4) << 3;
    const int kb_key   = wn * 32 + ((lane >> 4) << 3) + (lane & 7);
    const int kb_coff  = ((lane >> 3) & 1) << 3;
    const int vb_key   = wn * 32 + (lane & 15);
    const int vb_coff  = (lane >> 4) << 3;
    const int rA = wm * 16 + (lane >> 2);
    const int rB = rA + 8;
    const int qA = q0 + rA, qB = q0 + rB;

    for (int kt = 0; kt < SEQ / 64; kt++) {
        CPA_WAIT0();
        __syncthreads();
        if (kt + 1 < SEQ / 64) { load_kv(kt + 1); CPA_COMMIT(); }

        const uint32_t uKH = sb + KV_BASE + (kt & 1) * KV_STAGE;
        const uint32_t uKL = uKH + 9216;
        const uint32_t uVH = uKH + 18432;
        const uint32_t uVL = uKH + 27648;

        // ---- S = Q K^T ----
        float sS[4][4];
#pragma unroll
        for (int f = 0; f < 4; f++)
#pragma unroll
            for (int e = 0; e < 4; e++) sS[f][e] = 0.f;

#pragma unroll
        for (int ks = 0; ks < 4; ks++) {
            const uint32_t qoff = (uint32_t)(qa_row * QSTR + ks * 16 + qa_coff) * 2;
            uint32_t qh[4], ql[4];
            ldsm_x4(qh[0], qh[1], qh[2], qh[3], sb + OFF_QH + qoff);
            ldsm_x4(ql[0], ql[1], ql[2], ql[3], sb + OFF_QL + qoff);
            const uint32_t koff0 = (uint32_t)(kb_key * QSTR + ks * 16 + kb_coff) * 2;
            const uint32_t koff1 = (uint32_t)((kb_key + 16) * QSTR + ks * 16 + kb_coff) * 2;
            uint32_t kh0[4], kl0[4], kh1[4], kl1[4];
            ldsm_x4(kh0[0], kh0[1], kh0[2], kh0[3], uKH + koff0);
            ldsm_x4(kl0[0], kl0[1], kl0[2], kl0[3], uKL + koff0);
            ldsm_x4(kh1[0], kh1[1], kh1[2], kh1[3], uKH + koff1);
            ldsm_x4(kl1[0], kl1[1], kl1[2], kl1[3], uKL + koff1);
            mma16816(sS[0], qh, &kh0[0]);
            mma16816(sS[1], qh, &kh0[2]);
            mma16816(sS[2], qh, &kh1[0]);
            mma16816(sS[3], qh, &kh1[2]);
            mma16816(sS[0], qh, &kl0[0]);
            mma16816(sS[1], qh, &kl0[2]);
            mma16816(sS[2], qh, &kl1[0]);
            mma16816(sS[3], qh, &kl1[2]);
            mma16816(sS[0], ql, &kh0[0]);
            mma16816(sS[1], ql, &kh0[2]);
            mma16816(sS[2], ql, &kh1[0]);
            mma16816(sS[3], ql, &kh1[2]);
        }

        // ---- scale + relative bias ----
        const int kbase = kt * 64 + wn * 32 + (lane & 3) * 2;
#pragma unroll
        for (int f = 0; f < 4; f++) {
#pragma unroll
            for (int e = 0; e < 2; e++) {
                const int kg = kbase + f * 8 + e;
                int dA = kg - qA; dA = dA < 0 ? -dA : dA; if (dA > MAXD - 1) dA = MAXD - 1;
                int dB = kg - qB; dB = dB < 0 ? -dB : dB; if (dB > MAXD - 1) dB = MAXD - 1;
                sS[f][e]     = fmaf(sS[f][e],     0.125f, bias_s[dA]);
                sS[f][2 + e] = fmaf(sS[f][2 + e], 0.125f, bias_s[dB]);
            }
        }

        // ---- online softmax ----
        float mxA = fmaxf(fmaxf(sS[0][0], sS[0][1]), fmaxf(sS[1][0], sS[1][1]));
        mxA = fmaxf(mxA, fmaxf(fmaxf(sS[2][0], sS[2][1]), fmaxf(sS[3][0], sS[3][1])));
        float mxB = fmaxf(fmaxf(sS[0][2], sS[0][3]), fmaxf(sS[1][2], sS[1][3]));
        mxB = fmaxf(mxB, fmaxf(fmaxf(sS[2][2], sS[2][3]), fmaxf(sS[3][2], sS[3][3])));
        mxA = fmaxf(mxA, __shfl_xor_sync(0xffffffffu, mxA, 1));
        mxA = fmaxf(mxA, __shfl_xor_sync(0xffffffffu, mxA, 2));
        mxB = fmaxf(mxB, __shfl_xor_sync(0xffffffffu, mxB, 1));
        mxB = fmaxf(mxB, __shfl_xor_sync(0xffffffffu, mxB, 2));
        if ((lane & 3) == 0) { redM[wn * 64 + rA] = mxA; redM[wn * 64 + rB] = mxB; }
        __syncthreads();
        mxA = fmaxf(redM[rA], redM[64 + rA]);
        mxB = fmaxf(redM[rB], redM[64 + rB]);

        const float mnA = fmaxf(m_a, mxA), mnB = fmaxf(m_b, mxB);
        const float facA = __expf(m_a - mnA), facB = __expf(m_b - mnB);
        m_a = mnA; m_b = mnB;

        float sumA = 0.f, sumB = 0.f;
#pragma unroll
        for (int f = 0; f < 4; f++) {
#pragma unroll
            for (int e = 0; e < 2; e++) {
                sS[f][e]     = __expf(sS[f][e]     - m_a); sumA += sS[f][e];
                sS[f][2 + e] = __expf(sS[f][2 + e] - m_b); sumB += sS[f][2 + e];
            }
        }
        sumA += __shfl_xor_sync(0xffffffffu, sumA, 1);
        sumA += __shfl_xor_sync(0xffffffffu, sumA, 2);
        sumB += __shfl_xor_sync(0xffffffffu, sumB, 1);
        sumB += __shfl_xor_sync(0xffffffffu, sumB, 2);
        if ((lane & 3) == 0) { redS[wn * 64 + rA] = sumA; redS[wn * 64 + rB] = sumB; }
        __syncthreads();
        sumA = redS[rA] + redS[64 + rA];
        sumB = redS[rB] + redS[64 + rB];
        l_a = l_a * facA + sumA;
        l_b = l_b * facB + sumB;

#pragma unroll
        for (int d = 0; d < 8; d++) {
            accO[d][0] *= facA; accO[d][1] *= facA;
            accO[d][2] *= facB; accO[d][3] *= facB;
        }

        // ---- O += P V ----
#pragma unroll
        for (int ks2 = 0; ks2 < 2; ks2++) {
            uint32_t aH[4], aL[4];
            pack_hilo(sS[2 * ks2][0],     sS[2 * ks2][1],     aH[0], aL[0]);
            pack_hilo(sS[2 * ks2][2],     sS[2 * ks2][3],     aH[1], aL[1]);
            pack_hilo(sS[2 * ks2 + 1][0], sS[2 * ks2 + 1][1], aH[2], aL[2]);
            pack_hilo(sS[2 * ks2 + 1][2], sS[2 * ks2 + 1][3], aH[3], aL[3]);
            const int vrow = vb_key + ks2 * 16;
#pragma unroll
            for (int dp = 0; dp < 2; dp++) {
                const uint32_t voff0 =
                    (uint32_t)(vrow * QSTR + (2 * dp) * 16 + vb_coff) * 2;
                const uint32_t voff1 =
                    (uint32_t)(vrow * QSTR + (2 * dp + 1) * 16 + vb_coff) * 2;
                uint32_t vh0[4], vl0[4], vh1[4], vl1[4];
                ldsm_x4t(vh0[0], vh0[1], vh0[2], vh0[3], uVH + voff0);
                ldsm_x4t(vl0[0], vl0[1], vl0[2], vl0[3], uVL + voff0);
                ldsm_x4t(vh1[0], vh1[1], vh1[2], vh1[3], uVH + voff1);
                ldsm_x4t(vl1[0], vl1[1], vl1[2], vl1[3], uVL + voff1);
                mma16816(accO[4 * dp],     aH, &vh0[0]);
                mma16816(accO[4 * dp + 1], aH, &vh0[2]);
                mma16816(accO[4 * dp + 2], aH, &vh1[0]);
                mma16816(accO[4 * dp + 3], aH, &vh1[2]);
                mma16816(accO[4 * dp],     aH, &vl0[0]);
                mma16816(accO[4 * dp + 1], aH, &vl0[2]);
                mma16816(accO[4 * dp + 2], aH, &vl1[0]);
                mma16816(accO[4 * dp + 3], aH, &vl1[2]);
                mma16816(accO[4 * dp],     aL, &vh0[0]);
                mma16816(accO[4 * dp + 1], aL, &vh0[2]);
                mma16816(accO[4 * dp + 2], aL, &vh1[0]);
                mma16816(accO[4 * dp + 3], aL, &vh1[2]);
            }
        }
    }

    // ---- epilogue: cross-pair add + normalize + write bf16 hi/lo ----
    __syncthreads();
    float* Oep = (float*)(sm + OFF_OEP);
    const int ecol = (lane & 3) * 2;
    if (wn == 1) {
#pragma unroll
        for (int d = 0; d < 8; d++) {
            *(float2*)&Oep[rA * 68 + d * 8 + ecol] = make_float2(accO[d][0], accO[d][1]);
            *(float2*)&Oep[rB * 68 + d * 8 + ecol] = make_float2(accO[d][2], accO[d][3]);
        }
    }
    __syncthreads();
    if (wn == 0) {
        const float invA = 1.f / l_a, invB = 1.f / l_b;
#pragma unroll
        for (int d = 0; d < 8; d++) {
            float2 pA = *(float2*)&Oep[rA * 68 + d * 8 + ecol];
            float2 pB = *(float2*)&Oep[rB * 68 + d * 8 + ecol];
            uint32_t ph, pl;
            pack_hilo((accO[d][0] + pA.x) * invA, (accO[d][1] + pA.y) * invA, ph, pl);
            *(uint32_t*)(ath + (ull)qA * DM + h * DH + d * 8 + ecol) = ph;
            *(uint32_t*)(atl + (ull)qA * DM + h * DH + d * 8 + ecol) = pl;
            pack_hilo((accO[d][2] + pB.x) * invB, (accO[d][3] + pB.y) * invB, ph, pl);
            *(uint32_t*)(ath + (ull)qB * DM + h * DH + d * 8 + ecol) = ph;
            *(uint32_t*)(atl + (ull)qB * DM + h * DH + d * 8 + ecol) = pl;
        }
    }
}

// ---------------------------------------------------------------------------
extern "C" void kernel_launch(void* const* d_in, const int* in_sizes, int n_in,
                              void* d_out, int out_size) {
    const float* x        = (const float*)d_in[0];
    const float* w_qkv    = (const float*)d_in[1];
    const float* w_out    = (const float*)d_in[2];
    const float* rel_bias = (const float*)d_in[3];
    float* out = (float*)d_out;

    u16 *xh, *xl, *wqh, *wql, *woh, *wol, *qkvh, *qkvl, *ath, *atl;
    cudaGetSymbolAddress((void**)&xh,   g_xh);
    cudaGetSymbolAddress((void**)&xl,   g_xl);
    cudaGetSymbolAddress((void**)&wqh,  g_wqh);
    cudaGetSymbolAddress((void**)&wql,  g_wql);
    cudaGetSymbolAddress((void**)&woh,  g_woh);
    cudaGetSymbolAddress((void**)&wol,  g_wol);
    cudaGetSymbolAddress((void**)&qkvh, g_qkvh);
    cudaGetSymbolAddress((void**)&qkvl, g_qkvl);
    cudaGetSymbolAddress((void**)&ath,  g_ath);
    cudaGetSymbolAddress((void**)&atl,  g_atl);

    cudaFuncSetAttribute(gemm_bf16<true>,  cudaFuncAttributeMaxDynamicSharedMemorySize, GSMEM);
    cudaFuncSetAttribute(gemm_bf16<false>, cudaFuncAttributeMaxDynamicSharedMemorySize, GSMEM);
    cudaFuncSetAttribute(attn_mma, cudaFuncAttributeMaxDynamicSharedMemorySize, ATT_SMEM);

    // 0) one-time splits
    conv_split<<<(SEQ * DM / 4 + 255) / 256, 256>>>(x, xh, xl, SEQ * DM);
    conv_split<<<(DM * TDM / 4 + 255) / 256, 256>>>(w_qkv, wqh, wql, DM * TDM);
    conv_split<<<(DM * DM / 4 + 255) / 256, 256>>>(w_out, woh, wol, DM * DM);

    // 1) qkv = x @ w_qkv  -> bf16 hi/lo
    gemm_bf16<true><<<dim3(TDM / 128, SEQ / 128), 256, GSMEM>>>(
        xh, xl, wqh, wql, nullptr, qkvh, qkvl, SEQ, TDM, DM);

    // 2) attention -> bf16 hi/lo
    attn_mma<<<dim3(SEQ / 64, NH), 256, ATT_SMEM>>>(qkvh, qkvl, rel_bias, ath, atl);

    // 3) out = attn @ w_out -> fp32
    gemm_bf16<false><<<dim3(DM / 128, SEQ / 128), 256, GSMEM>>>(
        ath, atl, woh, wol, out, nullptr, nullptr, SEQ, DM, DM);
}

// round 9
// speedup vs baseline: 1.3705x; 1.0934x over previous
#include <cuda_runtime.h>
#include <cuda_bf16.h>
#include <cstdint>
#include <math.h>

#define SEQ  2048
#define DM   1024
#define TDM  3072
#define NH   16
#define DH   64
#define MAXD 128

typedef unsigned long long ull;
typedef unsigned short u16;

// ---------------- persistent scratch (bf16 hi/lo split form) ----------------
__device__ u16 g_xh[SEQ * DM],  g_xl[SEQ * DM];
__device__ u16 g_wqh[DM * TDM], g_wql[DM * TDM];
__device__ u16 g_woh[DM * DM],  g_wol[DM * DM];
__device__ u16 g_qkvh[SEQ * TDM], g_qkvl[SEQ * TDM];
__device__ u16 g_ath[SEQ * DM],   g_atl[SEQ * DM];

// ---------------- helpers ---------------------------------------------------
__device__ __forceinline__ uint32_t smem_u32(const void* p) {
    uint32_t a;
    asm("{ .reg .u64 t; cvta.to.shared.u64 t, %1; cvt.u32.u64 %0, t; }" : "=r"(a) : "l"(p));
    return a;
}
__device__ __forceinline__ void cpa16(uint32_t dst, const void* src) {
    asm volatile("cp.async.cg.shared.global [%0], [%1], 16;" :: "r"(dst), "l"(src));
}
#define CPA_COMMIT() asm volatile("cp.async.commit_group;" ::: "memory")
#define CPA_WAIT0()  asm volatile("cp.async.wait_group 0;" ::: "memory")

__device__ __forceinline__ void ldsm_x4(uint32_t& r0, uint32_t& r1, uint32_t& r2,
                                        uint32_t& r3, uint32_t addr) {
    asm volatile("ldmatrix.sync.aligned.m8n8.x4.shared.b16 {%0,%1,%2,%3}, [%4];"
                 : "=r"(r0), "=r"(r1), "=r"(r2), "=r"(r3) : "r"(addr));
}
__device__ __forceinline__ void ldsm_x4t(uint32_t& r0, uint32_t& r1, uint32_t& r2,
                                         uint32_t& r3, uint32_t addr) {
    asm volatile("ldmatrix.sync.aligned.m8n8.x4.trans.shared.b16 {%0,%1,%2,%3}, [%4];"
                 : "=r"(r0), "=r"(r1), "=r"(r2), "=r"(r3) : "r"(addr));
}
__device__ __forceinline__ void mma16816(float* d, const uint32_t* a, const uint32_t* b) {
    asm volatile("mma.sync.aligned.m16n8k16.row.col.f32.bf16.bf16.f32 "
                 "{%0,%1,%2,%3}, {%4,%5,%6,%7}, {%8,%9}, {%0,%1,%2,%3};"
                 : "+f"(d[0]), "+f"(d[1]), "+f"(d[2]), "+f"(d[3])
                 : "r"(a[0]), "r"(a[1]), "r"(a[2]), "r"(a[3]), "r"(b[0]), "r"(b[1]));
}
__device__ __forceinline__ uint32_t bf16x2_of(float lo, float hi) {
    uint32_t r;
    asm("cvt.rn.bf16x2.f32 %0, %1, %2;" : "=r"(r) : "f"(hi), "f"(lo));
    return r;
}
__device__ __forceinline__ void pack_hilo(float x, float y, uint32_t& ph, uint32_t& pl) {
    __nv_bfloat16 hx = __float2bfloat16_rn(x);
    __nv_bfloat16 hy = __float2bfloat16_rn(y);
    float fx = __bfloat162float(hx), fy = __bfloat162float(hy);
    ph = ((uint32_t)__bfloat16_as_ushort(hy) << 16) | (uint32_t)__bfloat16_as_ushort(hx);
    pl = bf16x2_of(x - fx, y - fy);
}

// ---------------------------------------------------------------------------
// One-time fp32 -> (hi,lo) bf16 split.
// ---------------------------------------------------------------------------
__global__ __launch_bounds__(256)
void conv_split(const float* __restrict__ src, u16* __restrict__ hi,
                u16* __restrict__ lo, int n) {
    int i = (blockIdx.x * 256 + threadIdx.x) * 4;
    if (i < n) {
        float4 v = *(const float4*)(src + i);
        uint32_t h0, l0, h1, l1;
        pack_hilo(v.x, v.y, h0, l0);
        pack_hilo(v.z, v.w, h1, l1);
        *(uint32_t*)(hi + i)     = h0;
        *(uint32_t*)(hi + i + 2) = h1;
        *(uint32_t*)(lo + i)     = l0;
        *(uint32_t*)(lo + i + 2) = l1;
    }
}

// ---------------------------------------------------------------------------
// Pure-bf16 split GEMM (validated R7): C = A @ B, pre-split inputs.
// ---------------------------------------------------------------------------
#define SA 40
#define SB 136
#define A_T_B 10240
#define B_T_B 8704
#define STAGE_B (2 * A_T_B + 2 * B_T_B)
#define GSMEM   (2 * STAGE_B)

template <bool WRITE_BF16>
__global__ __launch_bounds__(256, 2)
void gemm_bf16(const u16* __restrict__ Ah, const u16* __restrict__ Al,
               const u16* __restrict__ Bh, const u16* __restrict__ Bl,
               float* __restrict__ Cf, u16* __restrict__ Ch, u16* __restrict__ Cl,
               int M, int N, int K) {
    extern __shared__ char smem[];
    const uint32_t smem_b = smem_u32(smem);
    const int tid  = threadIdx.x;
    const int lane = tid & 31;
    const int wid  = tid >> 5;
    const int wm   = wid & 3;
    const int wn   = wid >> 2;
    const int bm = blockIdx.y * 128;
    const int bn = blockIdx.x * 128;

    auto load_stage = [&](int t) {
        const uint32_t stg = smem_b + (t & 1) * STAGE_B;
#pragma unroll
        for (int i = 0; i < 2; i++) {
            const int c = tid + i * 256;
            const int row = c >> 2, cc = c & 3;
            const ull sa = (ull)(bm + row) * K + t * 32 + cc * 8;
            cpa16(stg + row * 80 + cc * 16,         Ah + sa);
            cpa16(stg + A_T_B + row * 80 + cc * 16, Al + sa);
            const int rb = c >> 4, cb = c & 15;
            const ull sbp = (ull)(t * 32 + rb) * N + bn + cb * 8;
            cpa16(stg + 2 * A_T_B + rb * 272 + cb * 16,         Bh + sbp);
            cpa16(stg + 2 * A_T_B + B_T_B + rb * 272 + cb * 16, Bl + sbp);
        }
    };

    float acc[2][8][4];
#pragma unroll
    for (int mt = 0; mt < 2; mt++)
#pragma unroll
        for (int nt = 0; nt < 8; nt++)
#pragma unroll
            for (int e = 0; e < 4; e++) acc[mt][nt][e] = 0.f;

    const int NT = K / 32;
    load_stage(0);
    CPA_COMMIT();

    for (int t = 0; t < NT; t++) {
        CPA_WAIT0();
        __syncthreads();
        if (t + 1 < NT) { load_stage(t + 1); CPA_COMMIT(); }

        const uint32_t stg  = smem_b + (t & 1) * STAGE_B;
        const uint32_t uAhi = stg;
        const uint32_t uAlo = stg + A_T_B;
        const uint32_t uBhi = stg + 2 * A_T_B;
        const uint32_t uBlo = uBhi + B_T_B;
#pragma unroll
        for (int ks = 0; ks < 2; ks++) {
            const int k0 = ks * 16;
            uint32_t afh[2][4], afl[2][4];
#pragma unroll
            for (int mt = 0; mt < 2; mt++) {
                const int row = wm * 32 + mt * 16 + (lane & 15);
                const int col = k0 + ((lane >> 4) << 3);
                const uint32_t off = (uint32_t)(row * SA + col) * 2;
                ldsm_x4(afh[mt][0], afh[mt][1], afh[mt][2], afh[mt][3], uAhi + off);
                ldsm_x4(afl[mt][0], afl[mt][1], afl[mt][2], afl[mt][3], uAlo + off);
            }
#pragma unroll
            for (int g = 0; g < 4; g++) {
                uint32_t bh[4], bl[4];
                const int row = k0 + (lane & 15);
                const int col = wn * 64 + g * 16 + ((lane >> 4) << 3);
                const uint32_t off = (uint32_t)(row * SB + col) * 2;
                ldsm_x4t(bh[0], bh[1], bh[2], bh[3], uBhi + off);
                ldsm_x4t(bl[0], bl[1], bl[2], bl[3], uBlo + off);
                mma16816(acc[0][2 * g],     afh[0], &bh[0]);
                mma16816(acc[0][2 * g + 1], afh[0], &bh[2]);
                mma16816(acc[1][2 * g],     afh[1], &bh[0]);
                mma16816(acc[1][2 * g + 1], afh[1], &bh[2]);
                mma16816(acc[0][2 * g],     afh[0], &bl[0]);
                mma16816(acc[0][2 * g + 1], afh[0], &bl[2]);
                mma16816(acc[1][2 * g],     afh[1], &bl[0]);
                mma16816(acc[1][2 * g + 1], afh[1], &bl[2]);
                mma16816(acc[0][2 * g],     afl[0], &bh[0]);
                mma16816(acc[0][2 * g + 1], afl[0], &bh[2]);
                mma16816(acc[1][2 * g],     afl[1], &bh[0]);
                mma16816(acc[1][2 * g + 1], afl[1], &bh[2]);
            }
        }
    }

    const int group = lane >> 2;
    const int tq = lane & 3;
#pragma unroll
    for (int mt = 0; mt < 2; mt++) {
#pragma unroll
        for (int nt = 0; nt < 8; nt++) {
            const int row = bm + wm * 32 + mt * 16 + group;
            const int col = bn + wn * 64 + nt * 8 + tq * 2;
            if (WRITE_BF16) {
                uint32_t ph, pl;
                pack_hilo(acc[mt][nt][0], acc[mt][nt][1], ph, pl);
                *(uint32_t*)(Ch + (ull)row * N + col) = ph;
                *(uint32_t*)(Cl + (ull)row * N + col) = pl;
                pack_hilo(acc[mt][nt][2], acc[mt][nt][3], ph, pl);
                *(uint32_t*)(Ch + (ull)(row + 8) * N + col) = ph;
                *(uint32_t*)(Cl + (ull)(row + 8) * N + col) = pl;
            } else {
                *(float2*)&Cf[(ull)row * N + col] =
                    make_float2(acc[mt][nt][0], acc[mt][nt][1]);
                *(float2*)&Cf[(ull)(row + 8) * N + col] =
                    make_float2(acc[mt][nt][2], acc[mt][nt][3]);
            }
        }
    }
}

// ---------------------------------------------------------------------------
// HMMA flash attention, BQ=128: 8 warps, each owns 16 q-rows x ALL 64 keys.
// No cross-warp reductions; softmax fully in-quad.
// ---------------------------------------------------------------------------
#define QSTR 72
#define Q_BUF 18432               // 128*72*2
#define OFF_QH 0
#define OFF_QL Q_BUF
#define KV_BASE (2 * Q_BUF)       // 36864
#define KV_BUF 9216               // 64*72*2
#define KV_STAGE (4 * KV_BUF)     // KH,KL,VH,VL
#define OFF_BIAS (KV_BASE + 2 * KV_STAGE)   // 110592
#define ATT_SMEM (OFF_BIAS + 512)

__global__ __launch_bounds__(256, 2)
void attn_mma(const u16* __restrict__ qkvh, const u16* __restrict__ qkvl,
              const float* __restrict__ rel_bias,
              u16* __restrict__ ath, u16* __restrict__ atl) {
    extern __shared__ char sm[];
    const uint32_t sb = smem_u32(sm);
    const int tid  = threadIdx.x;
    const int lane = tid & 31;
    const int wm   = tid >> 5;           // warp = q-group (16 rows)
    const int h  = blockIdx.y;
    const int q0 = blockIdx.x * 128;

    float* bias_s = (float*)(sm + OFF_BIAS);
    if (tid < MAXD) bias_s[tid] = rel_bias[tid * NH + h];

    auto load_kv = [&](int kt) {
        const uint32_t sK = sb + KV_BASE + (kt & 1) * KV_STAGE;
        const ull base = (ull)(kt * 64) * TDM + h * DH;
#pragma unroll
        for (int i = 0; i < 2; i++) {
            const int c = tid + i * 256;
            const int row = c >> 3, cc = c & 7;
            const ull so = base + (ull)row * TDM + cc * 8;
            const uint32_t d = row * 144 + cc * 16;
            cpa16(sK + d,              qkvh + so + DM);
            cpa16(sK + KV_BUF + d,     qkvl + so + DM);
            cpa16(sK + 2 * KV_BUF + d, qkvh + so + 2 * DM);
            cpa16(sK + 3 * KV_BUF + d, qkvl + so + 2 * DM);
        }
    };

    // prologue: Q (128 rows) + KV tile 0
#pragma unroll
    for (int i = 0; i < 4; i++) {
        const int c = tid + i * 256;
        const int row = c >> 3, cc = c & 7;
        const ull so = (ull)(q0 + row) * TDM + h * DH + cc * 8;
        const uint32_t d = row * 144 + cc * 16;
        cpa16(sb + OFF_QH + d, qkvh + so);
        cpa16(sb + OFF_QL + d, qkvl + so);
    }
    load_kv(0);
    CPA_COMMIT();

    float m_a = -1e30f, m_b = -1e30f, l_a = 0.f, l_b = 0.f;
    float accO[8][4];
#pragma unroll
    for (int d = 0; d < 8; d++)
#pragma unroll
        for (int e = 0; e < 4; e++) accO[d][e] = 0.f;

    const int qa_row  = wm * 16 + (lane & 15);
    const int qa_coff = (lane >> 4) << 3;
    const int kb_key  = ((lane >> 4) << 3) + (lane & 7);
    const int kb_coff = ((lane >> 3) & 1) << 3;
    const int vb_key  = lane & 15;
    const int vb_coff = (lane >> 4) << 3;
    const int rA = wm * 16 + (lane >> 2);
    const int rB = rA + 8;
    const int qA = q0 + rA, qB = q0 + rB;

    for (int kt = 0; kt < SEQ / 64; kt++) {
        CPA_WAIT0();
        __syncthreads();
        if (kt + 1 < SEQ / 64) { load_kv(kt + 1); CPA_COMMIT(); }

        const uint32_t uKH = sb + KV_BASE + (kt & 1) * KV_STAGE;
        const uint32_t uKL = uKH + KV_BUF;
        const uint32_t uVH = uKH + 2 * KV_BUF;
        const uint32_t uVL = uKH + 3 * KV_BUF;

        // ---- S = Q K^T : 8 n-frags (64 keys) per warp ----
        float sS[8][4];
#pragma unroll
        for (int f = 0; f < 8; f++)
#pragma unroll
            for (int e = 0; e < 4; e++) sS[f][e] = 0.f;

#pragma unroll
        for (int ks = 0; ks < 4; ks++) {
            const uint32_t qoff = (uint32_t)(qa_row * QSTR + ks * 16 + qa_coff) * 2;
            uint32_t qh[4], ql[4];
            ldsm_x4(qh[0], qh[1], qh[2], qh[3], sb + OFF_QH + qoff);
            ldsm_x4(ql[0], ql[1], ql[2], ql[3], sb + OFF_QL + qoff);
#pragma unroll
            for (int kg = 0; kg < 2; kg++) {
                const uint32_t koff0 =
                    (uint32_t)((kb_key + kg * 32) * QSTR + ks * 16 + kb_coff) * 2;
                const uint32_t koff1 =
                    (uint32_t)((kb_key + kg * 32 + 16) * QSTR + ks * 16 + kb_coff) * 2;
                uint32_t kh0[4], kl0[4], kh1[4], kl1[4];
                ldsm_x4(kh0[0], kh0[1], kh0[2], kh0[3], uKH + koff0);
                ldsm_x4(kl0[0], kl0[1], kl0[2], kl0[3], uKL + koff0);
                ldsm_x4(kh1[0], kh1[1], kh1[2], kh1[3], uKH + koff1);
                ldsm_x4(kl1[0], kl1[1], kl1[2], kl1[3], uKL + koff1);
                float* s0 = sS[4 * kg + 0];
                float* s1 = sS[4 * kg + 1];
                float* s2 = sS[4 * kg + 2];
                float* s3 = sS[4 * kg + 3];
                mma16816(s0, qh, &kh0[0]);
                mma16816(s1, qh, &kh0[2]);
                mma16816(s2, qh, &kh1[0]);
                mma16816(s3, qh, &kh1[2]);
                mma16816(s0, qh, &kl0[0]);
                mma16816(s1, qh, &kl0[2]);
                mma16816(s2, qh, &kl1[0]);
                mma16816(s3, qh, &kl1[2]);
                mma16816(s0, ql, &kh0[0]);
                mma16816(s1, ql, &kh0[2]);
                mma16816(s2, ql, &kh1[0]);
                mma16816(s3, ql, &kh1[2]);
            }
        }

        // ---- scale + relative bias ----
        const int kbase = kt * 64 + (lane & 3) * 2;
#pragma unroll
        for (int f = 0; f < 8; f++) {
#pragma unroll
            for (int e = 0; e < 2; e++) {
                const int kg = kbase + f * 8 + e;
                int dA = kg - qA; dA = dA < 0 ? -dA : dA; if (dA > MAXD - 1) dA = MAXD - 1;
                int dB = kg - qB; dB = dB < 0 ? -dB : dB; if (dB > MAXD - 1) dB = MAXD - 1;
                sS[f][e]     = fmaf(sS[f][e],     0.125f, bias_s[dA]);
                sS[f][2 + e] = fmaf(sS[f][2 + e], 0.125f, bias_s[dB]);
            }
        }

        // ---- online softmax (fully in-quad) ----
        float mxA = -1e30f, mxB = -1e30f;
#pragma unroll
        for (int f = 0; f < 8; f++) {
            mxA = fmaxf(mxA, fmaxf(sS[f][0], sS[f][1]));
            mxB = fmaxf(mxB, fmaxf(sS[f][2], sS[f][3]));
        }
        mxA = fmaxf(mxA, __shfl_xor_sync(0xffffffffu, mxA, 1));
        mxA = fmaxf(mxA, __shfl_xor_sync(0xffffffffu, mxA, 2));
        mxB = fmaxf(mxB, __shfl_xor_sync(0xffffffffu, mxB, 1));
        mxB = fmaxf(mxB, __shfl_xor_sync(0xffffffffu, mxB, 2));

        const float mnA = fmaxf(m_a, mxA), mnB = fmaxf(m_b, mxB);
        const float facA = __expf(m_a - mnA), facB = __expf(m_b - mnB);
        m_a = mnA; m_b = mnB;

        float sumA = 0.f, sumB = 0.f;
#pragma unroll
        for (int f = 0; f < 8; f++) {
#pragma unroll
            for (int e = 0; e < 2; e++) {
                sS[f][e]     = __expf(sS[f][e]     - m_a); sumA += sS[f][e];
                sS[f][2 + e] = __expf(sS[f][2 + e] - m_b); sumB += sS[f][2 + e];
            }
        }
        sumA += __shfl_xor_sync(0xffffffffu, sumA, 1);
        sumA += __shfl_xor_sync(0xffffffffu, sumA, 2);
        sumB += __shfl_xor_sync(0xffffffffu, sumB, 1);
        sumB += __shfl_xor_sync(0xffffffffu, sumB, 2);
        l_a = l_a * facA + sumA;
        l_b = l_b * facB + sumB;

#pragma unroll
        for (int d = 0; d < 8; d++) {
            accO[d][0] *= facA; accO[d][1] *= facA;
            accO[d][2] *= facB; accO[d][3] *= facB;
        }

        // ---- O += P V : 4 key chunks of 16 ----
#pragma unroll
        for (int ks2 = 0; ks2 < 4; ks2++) {
            uint32_t aH[4], aL[4];
            pack_hilo(sS[2 * ks2][0],     sS[2 * ks2][1],     aH[0], aL[0]);
            pack_hilo(sS[2 * ks2][2],     sS[2 * ks2][3],     aH[1], aL[1]);
            pack_hilo(sS[2 * ks2 + 1][0], sS[2 * ks2 + 1][1], aH[2], aL[2]);
            pack_hilo(sS[2 * ks2 + 1][2], sS[2 * ks2 + 1][3], aH[3], aL[3]);
            const int vrow = vb_key + ks2 * 16;
#pragma unroll
            for (int dp = 0; dp < 2; dp++) {
                const uint32_t voff0 =
                    (uint32_t)(vrow * QSTR + (2 * dp) * 16 + vb_coff) * 2;
                const uint32_t voff1 =
                    (uint32_t)(vrow * QSTR + (2 * dp + 1) * 16 + vb_coff) * 2;
                uint32_t vh0[4], vl0[4], vh1[4], vl1[4];
                ldsm_x4t(vh0[0], vh0[1], vh0[2], vh0[3], uVH + voff0);
                ldsm_x4t(vl0[0], vl0[1], vl0[2], vl0[3], uVL + voff0);
                ldsm_x4t(vh1[0], vh1[1], vh1[2], vh1[3], uVH + voff1);
                ldsm_x4t(vl1[0], vl1[1], vl1[2], vl1[3], uVL + voff1);
                mma16816(accO[4 * dp],     aH, &vh0[0]);
                mma16816(accO[4 * dp + 1], aH, &vh0[2]);
                mma16816(accO[4 * dp + 2], aH, &vh1[0]);
                mma16816(accO[4 * dp + 3], aH, &vh1[2]);
                mma16816(accO[4 * dp],     aH, &vl0[0]);
                mma16816(accO[4 * dp + 1], aH, &vl0[2]);
                mma16816(accO[4 * dp + 2], aH, &vl1[0]);
                mma16816(accO[4 * dp + 3], aH, &vl1[2]);
                mma16816(accO[4 * dp],     aL, &vh0[0]);
                mma16816(accO[4 * dp + 1], aL, &vh0[2]);
                mma16816(accO[4 * dp + 2], aL, &vh1[0]);
                mma16816(accO[4 * dp + 3], aL, &vh1[2]);
            }
        }
    }

    // ---- epilogue: normalize + write bf16 hi/lo (no cross-warp add) ----
    const float invA = 1.f / l_a, invB = 1.f / l_b;
    const int ecol = (lane & 3) * 2;
#pragma unroll
    for (int d = 0; d < 8; d++) {
        uint32_t ph, pl;
        pack_hilo(accO[d][0] * invA, accO[d][1] * invA, ph, pl);
        *(uint32_t*)(ath + (ull)qA * DM + h * DH + d * 8 + ecol) = ph;
        *(uint32_t*)(atl + (ull)qA * DM + h * DH + d * 8 + ecol) = pl;
        pack_hilo(accO[d][2] * invB, accO[d][3] * invB, ph, pl);
        *(uint32_t*)(ath + (ull)qB * DM + h * DH + d * 8 + ecol) = ph;
        *(uint32_t*)(atl + (ull)qB * DM + h * DH + d * 8 + ecol) = pl;
    }
}

// ---------------------------------------------------------------------------
extern "C" void kernel_launch(void* const* d_in, const int* in_sizes, int n_in,
                              void* d_out, int out_size) {
    const float* x        = (const float*)d_in[0];
    const float* w_qkv    = (const float*)d_in[1];
    const float* w_out    = (const float*)d_in[2];
    const float* rel_bias = (const float*)d_in[3];
    float* out = (float*)d_out;

    u16 *xh, *xl, *wqh, *wql, *woh, *wol, *qkvh, *qkvl, *ath, *atl;
    cudaGetSymbolAddress((void**)&xh,   g_xh);
    cudaGetSymbolAddress((void**)&xl,   g_xl);
    cudaGetSymbolAddress((void**)&wqh,  g_wqh);
    cudaGetSymbolAddress((void**)&wql,  g_wql);
    cudaGetSymbolAddress((void**)&woh,  g_woh);
    cudaGetSymbolAddress((void**)&wol,  g_wol);
    cudaGetSymbolAddress((void**)&qkvh, g_qkvh);
    cudaGetSymbolAddress((void**)&qkvl, g_qkvl);
    cudaGetSymbolAddress((void**)&ath,  g_ath);
    cudaGetSymbolAddress((void**)&atl,  g_atl);

    cudaFuncSetAttribute(gemm_bf16<true>,  cudaFuncAttributeMaxDynamicSharedMemorySize, GSMEM);
    cudaFuncSetAttribute(gemm_bf16<false>, cudaFuncAttributeMaxDynamicSharedMemorySize, GSMEM);
    cudaFuncSetAttribute(attn_mma, cudaFuncAttributeMaxDynamicSharedMemorySize, ATT_SMEM);

    // 0) one-time splits
    conv_split<<<(SEQ * DM / 4 + 255) / 256, 256>>>(x, xh, xl, SEQ * DM);
    conv_split<<<(DM * TDM / 4 + 255) / 256, 256>>>(w_qkv, wqh, wql, DM * TDM);
    conv_split<<<(DM * DM / 4 + 255) / 256, 256>>>(w_out, woh, wol, DM * DM);

    // 1) qkv = x @ w_qkv  -> bf16 hi/lo
    gemm_bf16<true><<<dim3(TDM / 128, SEQ / 128), 256, GSMEM>>>(
        xh, xl, wqh, wql, nullptr, qkvh, qkvl, SEQ, TDM, DM);

    // 2) attention (BQ=128, warp-owns-row) -> bf16 hi/lo
    attn_mma<<<dim3(SEQ / 128, NH), 256, ATT_SMEM>>>(qkvh, qkvl, rel_bias, ath, atl);

    // 3) out = attn @ w_out -> fp32
    gemm_bf16<false><<<dim3(DM / 128, SEQ / 128), 256, GSMEM>>>(
        ath, atl, woh, wol, out, nullptr, nullptr, SEQ, DM, DM);
}

// round 11
// speedup vs baseline: 1.3818x; 1.0083x over previous
#include <cuda_runtime.h>
#include <cuda_bf16.h>
#include <cstdint>
#include <math.h>

#define SEQ  2048
#define DM   1024
#define TDM  3072
#define NH   16
#define DH   64
#define MAXD 128

typedef unsigned long long ull;
typedef unsigned short u16;

// ---------------- persistent scratch (bf16 hi/lo split form) ----------------
__device__ u16 g_xh[SEQ * DM],  g_xl[SEQ * DM];
__device__ u16 g_wqh[DM * TDM], g_wql[DM * TDM];
__device__ u16 g_woh[DM * DM],  g_wol[DM * DM];
__device__ u16 g_qkvh[SEQ * TDM], g_qkvl[SEQ * TDM];
__device__ u16 g_ath[SEQ * DM],   g_atl[SEQ * DM];

// ---------------- helpers ---------------------------------------------------
__device__ __forceinline__ uint32_t smem_u32(const void* p) {
    uint32_t a;
    asm("{ .reg .u64 t; cvta.to.shared.u64 t, %1; cvt.u32.u64 %0, t; }" : "=r"(a) : "l"(p));
    return a;
}
__device__ __forceinline__ void cpa16(uint32_t dst, const void* src) {
    asm volatile("cp.async.cg.shared.global [%0], [%1], 16;" :: "r"(dst), "l"(src));
}
#define CPA_COMMIT() asm volatile("cp.async.commit_group;" ::: "memory")
#define CPA_WAIT0()  asm volatile("cp.async.wait_group 0;" ::: "memory")

__device__ __forceinline__ void ldsm_x4(uint32_t& r0, uint32_t& r1, uint32_t& r2,
                                        uint32_t& r3, uint32_t addr) {
    asm volatile("ldmatrix.sync.aligned.m8n8.x4.shared.b16 {%0,%1,%2,%3}, [%4];"
                 : "=r"(r0), "=r"(r1), "=r"(r2), "=r"(r3) : "r"(addr));
}
__device__ __forceinline__ void ldsm_x4t(uint32_t& r0, uint32_t& r1, uint32_t& r2,
                                         uint32_t& r3, uint32_t addr) {
    asm volatile("ldmatrix.sync.aligned.m8n8.x4.trans.shared.b16 {%0,%1,%2,%3}, [%4];"
                 : "=r"(r0), "=r"(r1), "=r"(r2), "=r"(r3) : "r"(addr));
}
__device__ __forceinline__ void mma16816(float* d, const uint32_t* a, const uint32_t* b) {
    asm volatile("mma.sync.aligned.m16n8k16.row.col.f32.bf16.bf16.f32 "
                 "{%0,%1,%2,%3}, {%4,%5,%6,%7}, {%8,%9}, {%0,%1,%2,%3};"
                 : "+f"(d[0]), "+f"(d[1]), "+f"(d[2]), "+f"(d[3])
                 : "r"(a[0]), "r"(a[1]), "r"(a[2]), "r"(a[3]), "r"(b[0]), "r"(b[1]));
}
__device__ __forceinline__ uint32_t bf16x2_of(float lo, float hi) {
    uint32_t r;
    asm("cvt.rn.bf16x2.f32 %0, %1, %2;" : "=r"(r) : "f"(hi), "f"(lo));
    return r;
}
__device__ __forceinline__ void pack_hilo(float x, float y, uint32_t& ph, uint32_t& pl) {
    __nv_bfloat16 hx = __float2bfloat16_rn(x);
    __nv_bfloat16 hy = __float2bfloat16_rn(y);
    float fx = __bfloat162float(hx), fy = __bfloat162float(hy);
    ph = ((uint32_t)__bfloat16_as_ushort(hy) << 16) | (uint32_t)__bfloat16_as_ushort(hx);
    pl = bf16x2_of(x - fx, y - fy);
}

// ---------------------------------------------------------------------------
// One-time fp32 -> (hi,lo) bf16 split.
// ---------------------------------------------------------------------------
__global__ __launch_bounds__(256)
void conv_split(const float* __restrict__ src, u16* __restrict__ hi,
                u16* __restrict__ lo, int n) {
    int i = (blockIdx.x * 256 + threadIdx.x) * 4;
    if (i < n) {
        float4 v = *(const float4*)(src + i);
        uint32_t h0, l0, h1, l1;
        pack_hilo(v.x, v.y, h0, l0);
        pack_hilo(v.z, v.w, h1, l1);
        *(uint32_t*)(hi + i)     = h0;
        *(uint32_t*)(hi + i + 2) = h1;
        *(uint32_t*)(lo + i)     = l0;
        *(uint32_t*)(lo + i + 2) = l1;
    }
}

// ---------------------------------------------------------------------------
// Pure-bf16 split GEMM: C = A @ B, pre-split inputs.
// CTA 64x128, 128 threads = 4 warps (2 wm x 2 wn), warp tile 32x64.
// 4 CTAs/SM -> 4 independent pipelines per SM (finer barrier grain).
// ---------------------------------------------------------------------------
#define SA 40
#define SB 136
#define A_T_B 5120                  // 64*40*2 per term
#define B_T_B 8704                  // 32*136*2 per term
#define STAGE_B (2 * A_T_B + 2 * B_T_B)   // 27648
#define GSMEM   (2 * STAGE_B)             // 55296

template <bool WRITE_BF16>
__global__ __launch_bounds__(128, 4)
void gemm_bf16_v2(const u16* __restrict__ Ah, const u16* __restrict__ Al,
                  const u16* __restrict__ Bh, const u16* __restrict__ Bl,
                  float* __restrict__ Cf, u16* __restrict__ Ch, u16* __restrict__ Cl,
                  int M, int N, int K) {
    extern __shared__ char smem[];
    const uint32_t smem_b = smem_u32(smem);
    const int tid  = threadIdx.x;
    const int lane = tid & 31;
    const int wid  = tid >> 5;
    const int wm   = wid & 1;       // 2 m-groups of 32 rows
    const int wn   = wid >> 1;      // 2 n-groups of 64 cols
    const int bm = blockIdx.y * 64;
    const int bn = blockIdx.x * 128;

    auto load_stage = [&](int t) {
        const uint32_t stg = smem_b + (t & 1) * STAGE_B;
        // A: 64 rows x 32 cols bf16, hi+lo.
#pragma unroll
        for (int i = 0; i < 2; i++) {
            const int c = tid + i * 128;
            const int row = c >> 2, cc = c & 3;
            const ull sa = (ull)(bm + row) * K + t * 32 + cc * 8;
            cpa16(stg + row * 80 + cc * 16,         Ah + sa);
            cpa16(stg + A_T_B + row * 80 + cc * 16, Al + sa);
        }
        // B: 32 rows x 128 cols bf16, hi+lo.
#pragma unroll
        for (int i = 0; i < 4; i++) {
            const int c = tid + i * 128;
            const int rb = c >> 4, cb = c & 15;
            const ull sbp = (ull)(t * 32 + rb) * N + bn + cb * 8;
            cpa16(stg + 2 * A_T_B + rb * 272 + cb * 16,         Bh + sbp);
            cpa16(stg + 2 * A_T_B + B_T_B + rb * 272 + cb * 16, Bl + sbp);
        }
    };

    float accM0[8][4], accM1[8][4];
#pragma unroll
    for (int nt = 0; nt < 8; nt++)
#pragma unroll
        for (int e = 0; e < 4; e++) { accM0[nt][e] = 0.f; accM1[nt][e] = 0.f; }

    const int NT = K / 32;
    load_stage(0);
    CPA_COMMIT();

    for (int t = 0; t < NT; t++) {
        CPA_WAIT0();
        __syncthreads();
        if (t + 1 < NT) { load_stage(t + 1); CPA_COMMIT(); }

        const uint32_t stg  = smem_b + (t & 1) * STAGE_B;
        const uint32_t uAhi = stg;
        const uint32_t uAlo = stg + A_T_B;
        const uint32_t uBhi = stg + 2 * A_T_B;
        const uint32_t uBlo = uBhi + B_T_B;
#pragma unroll
        for (int ks = 0; ks < 2; ks++) {
            const int k0 = ks * 16;
            uint32_t afh0[4], afl0[4], afh1[4], afl1[4];
            {
                const int row0 = wm * 32 + (lane & 15);
                const int col = k0 + ((lane >> 4) << 3);
                const uint32_t off0 = (uint32_t)(row0 * SA + col) * 2;
                const uint32_t off1 = (uint32_t)((row0 + 16) * SA + col) * 2;
                ldsm_x4(afh0[0], afh0[1], afh0[2], afh0[3], uAhi + off0);
                ldsm_x4(afl0[0], afl0[1], afl0[2], afl0[3], uAlo + off0);
                ldsm_x4(afh1[0], afh1[1], afh1[2], afh1[3], uAhi + off1);
                ldsm_x4(afl1[0], afl1[1], afl1[2], afl1[3], uAlo + off1);
            }
#pragma unroll
            for (int g = 0; g < 4; g++) {
                uint32_t bh[4], bl[4];
                const int row = k0 + (lane & 15);
                const int col = wn * 64 + g * 16 + ((lane >> 4) << 3);
                const uint32_t off = (uint32_t)(row * SB + col) * 2;
                ldsm_x4t(bh[0], bh[1], bh[2], bh[3], uBhi + off);
                ldsm_x4t(bl[0], bl[1], bl[2], bl[3], uBlo + off);
                // hh (distance-4 chains across m0/m1 x n-halves)
                mma16816(accM0[2 * g],     afh0, &bh[0]);
                mma16816(accM0[2 * g + 1], afh0, &bh[2]);
                mma16816(accM1[2 * g],     afh1, &bh[0]);
                mma16816(accM1[2 * g + 1], afh1, &bh[2]);
                // hl
                mma16816(accM0[2 * g],     afh0, &bl[0]);
                mma16816(accM0[2 * g + 1], afh0, &bl[2]);
                mma16816(accM1[2 * g],     afh1, &bl[0]);
                mma16816(accM1[2 * g + 1], afh1, &bl[2]);
                // lh
                mma16816(accM0[2 * g],     afl0, &bh[0]);
                mma16816(accM0[2 * g + 1], afl0, &bh[2]);
                mma16816(accM1[2 * g],     afl1, &bh[0]);
                mma16816(accM1[2 * g + 1], afl1, &bh[2]);
            }
        }
    }

    // ---- epilogue ----
    const int group = lane >> 2;
    const int tq = lane & 3;
#pragma unroll
    for (int mt = 0; mt < 2; mt++) {
#pragma unroll
        for (int nt = 0; nt < 8; nt++) {
            float* a = (mt == 0) ? accM0[nt] : accM1[nt];
            const int row = bm + wm * 32 + mt * 16 + group;
            const int col = bn + wn * 64 + nt * 8 + tq * 2;
            if (WRITE_BF16) {
                uint32_t ph, pl;
                pack_hilo(a[0], a[1], ph, pl);
                *(uint32_t*)(Ch + (ull)row * N + col) = ph;
                *(uint32_t*)(Cl + (ull)row * N + col) = pl;
                pack_hilo(a[2], a[3], ph, pl);
                *(uint32_t*)(Ch + (ull)(row + 8) * N + col) = ph;
                *(uint32_t*)(Cl + (ull)(row + 8) * N + col) = pl;
            } else {
                *(float2*)&Cf[(ull)row * N + col] = make_float2(a[0], a[1]);
                *(float2*)&Cf[(ull)(row + 8) * N + col] = make_float2(a[2], a[3]);
            }
        }
    }
}

// ---------------------------------------------------------------------------
// HMMA flash attention, BQ=128 (R8, validated): 8 warps x 16 q-rows x 64 keys.
// ---------------------------------------------------------------------------
#define QSTR 72
#define Q_BUF 18432
#define OFF_QH 0
#define OFF_QL Q_BUF
#define KV_BASE (2 * Q_BUF)
#define KV_BUF 9216
#define KV_STAGE (4 * KV_BUF)
#define OFF_BIAS (KV_BASE + 2 * KV_STAGE)
#define ATT_SMEM (OFF_BIAS + 512)

__global__ __launch_bounds__(256, 2)
void attn_mma(const u16* __restrict__ qkvh, const u16* __restrict__ qkvl,
              const float* __restrict__ rel_bias,
              u16* __restrict__ ath, u16* __restrict__ atl) {
    extern __shared__ char sm[];
    const uint32_t sb = smem_u32(sm);
    const int tid  = threadIdx.x;
    const int lane = tid & 31;
    const int wm   = tid >> 5;
    const int h  = blockIdx.y;
    const int q0 = blockIdx.x * 128;

    float* bias_s = (float*)(sm + OFF_BIAS);
    if (tid < MAXD) bias_s[tid] = rel_bias[tid * NH + h];

    auto load_kv = [&](int kt) {
        const uint32_t sK = sb + KV_BASE + (kt & 1) * KV_STAGE;
        const ull base = (ull)(kt * 64) * TDM + h * DH;
#pragma unroll
        for (int i = 0; i < 2; i++) {
            const int c = tid + i * 256;
            const int row = c >> 3, cc = c & 7;
            const ull so = base + (ull)row * TDM + cc * 8;
            const uint32_t d = row * 144 + cc * 16;
            cpa16(sK + d,              qkvh + so + DM);
            cpa16(sK + KV_BUF + d,     qkvl + so + DM);
            cpa16(sK + 2 * KV_BUF + d, qkvh + so + 2 * DM);
            cpa16(sK + 3 * KV_BUF + d, qkvl + so + 2 * DM);
        }
    };

#pragma unroll
    for (int i = 0; i < 4; i++) {
        const int c = tid + i * 256;
        const int row = c >> 3, cc = c & 7;
        const ull so = (ull)(q0 + row) * TDM + h * DH + cc * 8;
        const uint32_t d = row * 144 + cc * 16;
        cpa16(sb + OFF_QH + d, qkvh + so);
        cpa16(sb + OFF_QL + d, qkvl + so);
    }
    load_kv(0);
    CPA_COMMIT();

    float m_a = -1e30f, m_b = -1e30f, l_a = 0.f, l_b = 0.f;
    float accO[8][4];
#pragma unroll
    for (int d = 0; d < 8; d++)
#pragma unroll
        for (int e = 0; e < 4; e++) accO[d][e] = 0.f;

    const int qa_row  = wm * 16 + (lane & 15);
    const int qa_coff = (lane >> 4) << 3;
    const int kb_key  = ((lane >> 4) << 3) + (lane & 7);
    const int kb_coff = ((lane >> 3) & 1) << 3;
    const int vb_key  = lane & 15;
    const int vb_coff = (lane >> 4) << 3;
    const int rA = wm * 16 + (lane >> 2);
    const int rB = rA + 8;
    const int qA = q0 + rA, qB = q0 + rB;

    for (int kt = 0; kt < SEQ / 64; kt++) {
        CPA_WAIT0();
        __syncthreads();
        if (kt + 1 < SEQ / 64) { load_kv(kt + 1); CPA_COMMIT(); }

        const uint32_t uKH = sb + KV_BASE + (kt & 1) * KV_STAGE;
        const uint32_t uKL = uKH + KV_BUF;
        const uint32_t uVH = uKH + 2 * KV_BUF;
        const uint32_t uVL = uKH + 3 * KV_BUF;

        float sS[8][4];
#pragma unroll
        for (int f = 0; f < 8; f++)
#pragma unroll
            for (int e = 0; e < 4; e++) sS[f][e] = 0.f;

#pragma unroll
        for (int ks = 0; ks < 4; ks++) {
            const uint32_t qoff = (uint32_t)(qa_row * QSTR + ks * 16 + qa_coff) * 2;
            uint32_t qh[4], ql[4];
            ldsm_x4(qh[0], qh[1], qh[2], qh[3], sb + OFF_QH + qoff);
            ldsm_x4(ql[0], ql[1], ql[2], ql[3], sb + OFF_QL + qoff);
#pragma unroll
            for (int kg = 0; kg < 2; kg++) {
                const uint32_t koff0 =
                    (uint32_t)((kb_key + kg * 32) * QSTR + ks * 16 + kb_coff) * 2;
                const uint32_t koff1 =
                    (uint32_t)((kb_key + kg * 32 + 16) * QSTR + ks * 16 + kb_coff) * 2;
                uint32_t kh0[4], kl0[4], kh1[4], kl1[4];
                ldsm_x4(kh0[0], kh0[1], kh0[2], kh0[3], uKH + koff0);
                ldsm_x4(kl0[0], kl0[1], kl0[2], kl0[3], uKL + koff0);
                ldsm_x4(kh1[0], kh1[1], kh1[2], kh1[3], uKH + koff1);
                ldsm_x4(kl1[0], kl1[1], kl1[2], kl1[3], uKL + koff1);
                float* s0 = sS[4 * kg + 0];
                float* s1 = sS[4 * kg + 1];
                float* s2 = sS[4 * kg + 2];
                float* s3 = sS[4 * kg + 3];
                mma16816(s0, qh, &kh0[0]);
                mma16816(s1, qh, &kh0[2]);
                mma16816(s2, qh, &kh1[0]);
                mma16816(s3, qh, &kh1[2]);
                mma16816(s0, qh, &kl0[0]);
                mma16816(s1, qh, &kl0[2]);
                mma16816(s2, qh, &kl1[0]);
                mma16816(s3, qh, &kl1[2]);
                mma16816(s0, ql, &kh0[0]);
                mma16816(s1, ql, &kh0[2]);
                mma16816(s2, ql, &kh1[0]);
                mma16816(s3, ql, &kh1[2]);
            }
        }

        const int kbase = kt * 64 + (lane & 3) * 2;
#pragma unroll
        for (int f = 0; f < 8; f++) {
#pragma unroll
            for (int e = 0; e < 2; e++) {
                const int kg = kbase + f * 8 + e;
                int dA = kg - qA; dA = dA < 0 ? -dA : dA; if (dA > MAXD - 1) dA = MAXD - 1;
                int dB = kg - qB; dB = dB < 0 ? -dB : dB; if (dB > MAXD - 1) dB = MAXD - 1;
                sS[f][e]     = fmaf(sS[f][e],     0.125f, bias_s[dA]);
                sS[f][2 + e] = fmaf(sS[f][2 + e], 0.125f, bias_s[dB]);
            }
        }

        float mxA = -1e30f, mxB = -1e30f;
#pragma unroll
        for (int f = 0; f < 8; f++) {
            mxA = fmaxf(mxA, fmaxf(sS[f][0], sS[f][1]));
            mxB = fmaxf(mxB, fmaxf(sS[f][2], sS[f][3]));
        }
        mxA = fmaxf(mxA, __shfl_xor_sync(0xffffffffu, mxA, 1));
        mxA = fmaxf(mxA, __shfl_xor_sync(0xffffffffu, mxA, 2));
        mxB = fmaxf(mxB, __shfl_xor_sync(0xffffffffu, mxB, 1));
        mxB = fmaxf(mxB, __shfl_xor_sync(0xffffffffu, mxB, 2));

        const float mnA = fmaxf(m_a, mxA), mnB = fmaxf(m_b, mxB);
        const float facA = __expf(m_a - mnA), facB = __expf(m_b - mnB);
        m_a = mnA; m_b = mnB;

        float sumA = 0.f, sumB = 0.f;
#pragma unroll
        for (int f = 0; f < 8; f++) {
#pragma unroll
            for (int e = 0; e < 2; e++) {
                sS[f][e]     = __expf(sS[f][e]     - m_a); sumA += sS[f][e];
                sS[f][2 + e] = __expf(sS[f][2 + e] - m_b); sumB += sS[f][2 + e];
            }
        }
        sumA += __shfl_xor_sync(0xffffffffu, sumA, 1);
        sumA += __shfl_xor_sync(0xffffffffu, sumA, 2);
        sumB += __shfl_xor_sync(0xffffffffu, sumB, 1);
        sumB += __shfl_xor_sync(0xffffffffu, sumB, 2);
        l_a = l_a * facA + sumA;
        l_b = l_b * facB + sumB;

#pragma unroll
        for (int d = 0; d < 8; d++) {
            accO[d][0] *= facA; accO[d][1] *= facA;
            accO[d][2] *= facB; accO[d][3] *= facB;
        }

#pragma unroll
        for (int ks2 = 0; ks2 < 4; ks2++) {
            uint32_t aH[4], aL[4];
            pack_hilo(sS[2 * ks2][0],     sS[2 * ks2][1],     aH[0], aL[0]);
            pack_hilo(sS[2 * ks2][2],     sS[2 * ks2][3],     aH[1], aL[1]);
            pack_hilo(sS[2 * ks2 + 1][0], sS[2 * ks2 + 1][1], aH[2], aL[2]);
            pack_hilo(sS[2 * ks2 + 1][2], sS[2 * ks2 + 1][3], aH[3], aL[3]);
            const int vrow = vb_key + ks2 * 16;
#pragma unroll
            for (int dp = 0; dp < 2; dp++) {
                const uint32_t voff0 =
                    (uint32_t)(vrow * QSTR + (2 * dp) * 16 + vb_coff) * 2;
                const uint32_t voff1 =
                    (uint32_t)(vrow * QSTR + (2 * dp + 1) * 16 + vb_coff) * 2;
                uint32_t vh0[4], vl0[4], vh1[4], vl1[4];
                ldsm_x4t(vh0[0], vh0[1], vh0[2], vh0[3], uVH + voff0);
                ldsm_x4t(vl0[0], vl0[1], vl0[2], vl0[3], uVL + voff0);
                ldsm_x4t(vh1[0], vh1[1], vh1[2], vh1[3], uVH + voff1);
                ldsm_x4t(vl1[0], vl1[1], vl1[2], vl1[3], uVL + voff1);
                mma16816(accO[4 * dp],     aH, &vh0[0]);
                mma16816(accO[4 * dp + 1], aH, &vh0[2]);
                mma16816(accO[4 * dp + 2], aH, &vh1[0]);
                mma16816(accO[4 * dp + 3], aH, &vh1[2]);
                mma16816(accO[4 * dp],     aH, &vl0[0]);
                mma16816(accO[4 * dp + 1], aH, &vl0[2]);
                mma16816(accO[4 * dp + 2], aH, &vl1[0]);
                mma16816(accO[4 * dp + 3], aH, &vl1[2]);
                mma16816(accO[4 * dp],     aL, &vh0[0]);
                mma16816(accO[4 * dp + 1], aL, &vh0[2]);
                mma16816(accO[4 * dp + 2], aL, &vh1[0]);
                mma16816(accO[4 * dp + 3], aL, &vh1[2]);
            }
        }
    }

    const float invA = 1.f / l_a, invB = 1.f / l_b;
    const int ecol = (lane & 3) * 2;
#pragma unroll
    for (int d = 0; d < 8; d++) {
        uint32_t ph, pl;
        pack_hilo(accO[d][0] * invA, accO[d][1] * invA, ph, pl);
        *(uint32_t*)(ath + (ull)qA * DM + h * DH + d * 8 + ecol) = ph;
        *(uint32_t*)(atl + (ull)qA * DM + h * DH + d * 8 + ecol) = pl;
        pack_hilo(accO[d][2] * invB, accO[d][3] * invB, ph, pl);
        *(uint32_t*)(ath + (ull)qB * DM + h * DH + d * 8 + ecol) = ph;
        *(uint32_t*)(atl + (ull)qB * DM + h * DH + d * 8 + ecol) = pl;
    }
}

// ---------------------------------------------------------------------------
extern "C" void kernel_launch(void* const* d_in, const int* in_sizes, int n_in,
                              void* d_out, int out_size) {
    const float* x        = (const float*)d_in[0];
    const float* w_qkv    = (const float*)d_in[1];
    const float* w_out    = (const float*)d_in[2];
    const float* rel_bias = (const float*)d_in[3];
    float* out = (float*)d_out;

    u16 *xh, *xl, *wqh, *wql, *woh, *wol, *qkvh, *qkvl, *ath, *atl;
    cudaGetSymbolAddress((void**)&xh,   g_xh);
    cudaGetSymbolAddress((void**)&xl,   g_xl);
    cudaGetSymbolAddress((void**)&wqh,  g_wqh);
    cudaGetSymbolAddress((void**)&wql,  g_wql);
    cudaGetSymbolAddress((void**)&woh,  g_woh);
    cudaGetSymbolAddress((void**)&wol,  g_wol);
    cudaGetSymbolAddress((void**)&qkvh, g_qkvh);
    cudaGetSymbolAddress((void**)&qkvl, g_qkvl);
    cudaGetSymbolAddress((void**)&ath,  g_ath);
    cudaGetSymbolAddress((void**)&atl,  g_atl);

    cudaFuncSetAttribute(gemm_bf16_v2<true>,  cudaFuncAttributeMaxDynamicSharedMemorySize, GSMEM);
    cudaFuncSetAttribute(gemm_bf16_v2<false>, cudaFuncAttributeMaxDynamicSharedMemorySize, GSMEM);
    cudaFuncSetAttribute(attn_mma, cudaFuncAttributeMaxDynamicSharedMemorySize, ATT_SMEM);

    // 0) one-time splits
    conv_split<<<(SEQ * DM / 4 + 255) / 256, 256>>>(x, xh, xl, SEQ * DM);
    conv_split<<<(DM * TDM / 4 + 255) / 256, 256>>>(w_qkv, wqh, wql, DM * TDM);
    conv_split<<<(DM * DM / 4 + 255) / 256, 256>>>(w_out, woh, wol, DM * DM);

    // 1) qkv = x @ w_qkv  -> bf16 hi/lo   (64x128 CTAs, 4/SM)
    gemm_bf16_v2<true><<<dim3(TDM / 128, SEQ / 64), 128, GSMEM>>>(
        xh, xl, wqh, wql, nullptr, qkvh, qkvl, SEQ, TDM, DM);

    // 2) attention (BQ=128, warp-owns-row) -> bf16 hi/lo
    attn_mma<<<dim3(SEQ / 128, NH), 256, ATT_SMEM>>>(qkvh, qkvl, rel_bias, ath, atl);

    // 3) out = attn @ w_out -> fp32
    gemm_bf16_v2<false><<<dim3(DM / 128, SEQ / 64), 128, GSMEM>>>(
        ath, atl, woh, wol, out, nullptr, nullptr, SEQ, DM, DM);
}